// round 11
// baseline (speedup 1.0000x reference)
#include <cuda_runtime.h>
#include <cuda_bf16.h>
#include <math.h>

// ---------------- problem constants ----------------
#define BB 4
#define TT_SEQ 4096
#define DD 1024
#define NTOK (BB*TT_SEQ)          // 16384
#define NBLK 16
#define BIP 192
#define RANKR 64
#define NMEM 128
#define EPSV 1.1920929e-07f
#define NT128 (NTOK/128)          // 128
#define NPOS 32
#define NCHAIN 64

// fragment-slot strides
#define ASLOT 132
#define BSLOT 66
#define BSZ (32*BSLOT)            // 2112 uints
#define ASZ64  (16*ASLOT)
#define ASZ128 (32*ASLOT)         // 4224 uints
#define SDS 66

// ---------------- scratch (device globals; no allocation) ----------------
__device__ __nv_bfloat16 g_xn[NTOK*DD];   // bf16(x*rsx), row-major
__device__ float g_rsx [NTOK];
__device__ float g_ssp [NTOK*16];

// decoupled-lookback state
__device__ int   g_ticket;
__device__ int   g_state[NCHAIN*NPOS];
__device__ float g_aggv [NCHAIN*NPOS*64];
__device__ float g_incv [NCHAIN*NPOS*64];

// fragment-major tensors (16B aligned for cp.async)
__device__ uint4 g_hnf[NT128*16*1056];    // UNNORMALIZED h, frag tiles [slab][chunk]
__device__ uint4 g_rf [NT128*16*1056];
__device__ uint4 g_tf [2*NT128*1056];     // two K-half partials of t

// pre-fragmented bf16 weights
__device__ uint4 g_wf_seq [NBLK*BSZ/4];
__device__ uint4 g_wf_dep [NBLK*BSZ/4];
__device__ uint4 g_wf_loc [NBLK*BSZ/4];
__device__ uint4 g_wf_lrA [NBLK*BSZ/4];
__device__ uint4 g_wf_post[NBLK*3*BSZ/4];
__device__ uint4 g_wf_lrB [16*BSZ/4];

__device__ __forceinline__ float siluf(float x) {
    return x / (1.0f + __expf(-x));
}

__device__ __forceinline__ unsigned pk(float a, float b) {
    unsigned r;
    asm("cvt.rn.bf16x2.f32 %0, %1, %2;" : "=r"(r) : "f"(b), "f"(a));
    return r;
}

__device__ __forceinline__ float decay1(const float* __restrict__ lA,
                                        const float* __restrict__ ldt, int d) {
    return fmaxf(__expf(-__expf(lA[d]) * __expf(ldt[d])), 1e-6f);
}

// ---------------- acquire/release ----------------
__device__ __forceinline__ int ld_acq(const int* p) {
    int v;
    asm volatile("ld.global.acquire.gpu.b32 %0, [%1];" : "=r"(v) : "l"(p));
    return v;
}
__device__ __forceinline__ void st_rel(int* p, int v) {
    asm volatile("st.global.release.gpu.b32 [%0], %1;" :: "l"(p), "r"(v));
}

// ---------------- cp.async helpers ----------------
__device__ __forceinline__ unsigned sptr(const void* p) {
    return (unsigned)__cvta_generic_to_shared(p);
}
__device__ __forceinline__ void cpa16(unsigned d, const void* s) {
    asm volatile("cp.async.cg.shared.global [%0], [%1], 16;" :: "r"(d), "l"(s));
}
__device__ __forceinline__ void cp_commit() {
    asm volatile("cp.async.commit_group;");
}
template<int N>
__device__ __forceinline__ void cp_wait() {
    asm volatile("cp.async.wait_group %0;" :: "n"(N));
}
template<int N4>
__device__ __forceinline__ void cpcopy(unsigned dsm, const uint4* __restrict__ src, int tid) {
#pragma unroll
    for (int i = tid; i < N4; i += 256) cpa16(dsm + i * 16, src + i);
}

// ---------------- bf16 MMA machinery ----------------
__device__ __forceinline__ void mma_bf16(float c[4], const unsigned a[4], const unsigned b[2]) {
    asm volatile("mma.sync.aligned.m16n8k16.row.col.f32.bf16.bf16.f32 "
        "{%0,%1,%2,%3}, {%4,%5,%6,%7}, {%8,%9}, {%0,%1,%2,%3};"
        : "+f"(c[0]), "+f"(c[1]), "+f"(c[2]), "+f"(c[3])
        : "r"(a[0]), "r"(a[1]), "r"(a[2]), "r"(a[3]), "r"(b[0]), "r"(b[1]));
}

__device__ __forceinline__ void putA16(unsigned* sA, int i, int j0, uint2 u) {
    int mt = i >> 4, rr = i & 15, half = rr >> 3, g = rr & 7;
    int ks = j0 >> 4, kk = j0 & 15, hi = kk >> 3, t0 = (kk & 7) >> 1;
    unsigned* p = &sA[(mt * 4 + ks) * ASLOT + (g * 4 + t0) * 4 + half + 2 * hi];
    p[0] = u.x;
    p[4] = u.y;
}

template<int M>
__device__ __forceinline__ void stageA16(unsigned* sA, const __nv_bfloat16* __restrict__ base,
                                         int rs, int tid) {
#pragma unroll
    for (int it = 0; it < M / 16; ++it) {
        int idx = tid + it * 256;
        int i  = idx >> 4;
        int j0 = (idx & 15) << 2;
        uint2 u = *reinterpret_cast<const uint2*>(base + (size_t)i * rs + j0);
        putA16(sA, i, j0, u);
    }
}

// register-prefetched row staging of one 128x64 chunk of xn
struct RowRegs { uint2 u[8]; };

__device__ __forceinline__ void row_load(RowRegs& r, int tok0, int gc, int tid) {
    bool shift = gc >= 32;
    int cc = shift ? gc - 32 : gc - 16;
#pragma unroll
    for (int it = 0; it < 8; ++it) {
        int idx = tid + it * 256;
        int i  = idx >> 4;
        int j0 = (idx & 15) << 2;
        int tok = tok0 + i;
        if (shift && (tok & (TT_SEQ - 1)) == 0) {
            r.u[it].x = 0u; r.u[it].y = 0u;
        } else {
            int st = shift ? tok - 1 : tok;
            r.u[it] = *reinterpret_cast<const uint2*>(&g_xn[(size_t)st * DD + cc * 64 + j0]);
        }
    }
}

__device__ __forceinline__ void row_sts(unsigned* sA, const RowRegs& r, int tid) {
#pragma unroll
    for (int it = 0; it < 8; ++it) {
        int idx = tid + it * 256;
        putA16(sA, idx >> 4, (idx & 15) << 2, r.u[it]);
    }
}

__device__ __forceinline__ void mma_chunk128(float acc[8][4], const unsigned* sA,
                                             const unsigned* sB, int w, int lane) {
#pragma unroll
    for (int ks = 0; ks < 4; ks++) {
        unsigned a[4];
        *reinterpret_cast<uint4*>(a) =
            *reinterpret_cast<const uint4*>(&sA[(w * 4 + ks) * ASLOT + lane * 4]);
#pragma unroll
        for (int nt = 0; nt < 8; nt++) {
            unsigned b[2];
            *reinterpret_cast<uint2*>(b) =
                *reinterpret_cast<const uint2*>(&sB[(nt * 4 + ks) * BSLOT + lane * 2]);
            mma_bf16(acc[nt], a, b);
        }
    }
}

__device__ __forceinline__ void mma_chunk64(float acc[4][4], const unsigned* sA,
                                            const unsigned* sB, int wm, int wn, int lane) {
#pragma unroll
    for (int ks = 0; ks < 4; ks++) {
        unsigned a[4];
        *reinterpret_cast<uint4*>(a) =
            *reinterpret_cast<const uint4*>(&sA[(wm * 4 + ks) * ASLOT + lane * 4]);
#pragma unroll
        for (int nt = 0; nt < 4; nt++) {
            unsigned b[2];
            *reinterpret_cast<uint2*>(b) =
                *reinterpret_cast<const uint2*>(&sB[((wn * 4 + nt) * 4 + ks) * BSLOT + lane * 2]);
            mma_bf16(acc[nt], a, b);
        }
    }
}

__device__ __forceinline__ void scale_acc(float acc[8][4], float ra, float rb) {
#pragma unroll
    for (int nt = 0; nt < 8; nt++) {
        acc[nt][0] *= ra; acc[nt][1] *= ra;
        acc[nt][2] *= rb; acc[nt][3] *= rb;
    }
}

// ---------------- prep: flags + weight fragmentation + rsx + xn ----------------
__global__ void __launch_bounds__(256) k_prep(const float* __restrict__ x,
                                              const float* __restrict__ wseq,
                                              const float* __restrict__ wdep,
                                              const float* __restrict__ wloc,
                                              const float* __restrict__ lrA,
                                              const float* __restrict__ wpost,
                                              const float* __restrict__ lrB) {
    int tid = threadIdx.x;
    if (blockIdx.x == 0) {
        if (tid == 0) g_ticket = 0;
        for (int i = tid; i < NCHAIN * NPOS; i += 256) g_state[i] = 0;
    }
    if (blockIdx.x < 128) {
        int t = blockIdx.x;
        const float* src;
        unsigned* dst;
        int rs;
        if (t < 16)       { src = wseq + (size_t)t * 4096; dst = (unsigned*)g_wf_seq + t * BSZ; rs = 64; }
        else if (t < 32)  { int b = t - 16; src = wdep + (size_t)b * 4096; dst = (unsigned*)g_wf_dep + b * BSZ; rs = 64; }
        else if (t < 48)  { int b = t - 32; src = wloc + (size_t)b * 4096; dst = (unsigned*)g_wf_loc + b * BSZ; rs = 64; }
        else if (t < 64)  { int b = t - 48; src = lrA + (size_t)b * 4096;  dst = (unsigned*)g_wf_lrA + b * BSZ; rs = 64; }
        else if (t < 112) { int i = t - 64; int b = i / 3, kt = i % 3;
                            src = wpost + (size_t)b * 64 * BIP + kt * 64;
                            dst = (unsigned*)g_wf_post + i * BSZ; rs = BIP; }
        else              { int kt = t - 112; src = lrB + kt * 64; dst = (unsigned*)g_wf_lrB + kt * BSZ; rs = DD; }
#pragma unroll
        for (int it = 0; it < 4; ++it) {
            int idx = tid + it * 256;
            int n  = idx >> 4;
            int k0 = (idx & 15) << 2;
            float4 v = *reinterpret_cast<const float4*>(src + (size_t)n * rs + k0);
            int nt = n >> 3, g = n & 7;
            int ks = k0 >> 4, kk = k0 & 15, hi = kk >> 3, t0 = (kk & 7) >> 1;
            unsigned* p = &dst[(nt * 4 + ks) * BSLOT + (g * 4 + t0) * 2 + hi];
            p[0] = pk(v.x, v.y);
            p[2] = pk(v.z, v.w);
        }
    } else {
        int w = tid >> 5, lane = tid & 31;
        int tok = (blockIdx.x - 128) * 8 + w;
        const float4* xr = reinterpret_cast<const float4*>(x + (size_t)tok * DD);
        float4 v[8];
        float ss = 0.0f;
#pragma unroll
        for (int i = 0; i < 8; i++) {
            v[i] = xr[lane + i * 32];
            ss += v[i].x * v[i].x + v[i].y * v[i].y + v[i].z * v[i].z + v[i].w * v[i].w;
        }
#pragma unroll
        for (int off = 16; off > 0; off >>= 1) ss += __shfl_xor_sync(0xffffffffu, ss, off);
        ss = __shfl_sync(0xffffffffu, ss, 0);
        float sc = rsqrtf(ss * (1.0f / DD) + EPSV);
        if (lane == 0) g_rsx[tok] = sc;
        uint2* xo = reinterpret_cast<uint2*>(g_xn + (size_t)tok * DD);
#pragma unroll
        for (int i = 0; i < 8; i++) {
            uint2 o;
            o.x = pk(v[i].x * sc, v[i].y * sc);
            o.y = pk(v[i].z * sc, v[i].w * sc);
            xo[lane + i * 32] = o;
        }
    }
}

// ---------------- gain helper ----------------
__device__ __forceinline__ float gain_of(int gch, float Kf, const float* __restrict__ lAd,
                                         const float* __restrict__ ldtd) {
    if (gch < NMEM) return Kf;
    float a1 = __expf(-__expf(lAd[gch - NMEM]) * __expf(ldtd[gch - NMEM]));
    float om = 1.0f - a1;
    if (fabsf(om) < 1e-6f) return Kf;
    return (1.0f - __expf(Kf * __logf(a1))) / fmaxf(om, 1e-8f);
}

// ---------------- G1S: GEMMs + single-pass scan -> g_hnf (frag) + g_ssp ----------------
#define G1SMEM (13248 * 4)

__global__ void __launch_bounds__(256) k_g1s(const float* __restrict__ lAd,
                                             const float* __restrict__ ldtd,
                                             const float* __restrict__ lAs,
                                             const float* __restrict__ ldts,
                                             const int* __restrict__ kptr) {
    extern __shared__ __align__(16) unsigned dyn[];
    __shared__ int s_ticket;
    int tid = threadIdx.x, lane = tid & 31, w = tid >> 5;

    if (tid == 0) s_ticket = atomicAdd(&g_ticket, 1);
    __syncthreads();
    int ticket = s_ticket;
    int chain = ticket & (NCHAIN - 1);
    int pos   = ticket >> 6;
    int b = chain >> 4, blk = chain & 15;
    int slab = b * NPOS + pos;
    int tok0 = slab * 128;

    unsigned* sA  = dyn;
    unsigned* sB1 = dyn + ASZ128;
    unsigned* sB2 = dyn + ASZ128 + BSZ;

    cpcopy<528>(sptr(sB1), g_wf_seq + (size_t)blk * 528, tid);
    cpcopy<528>(sptr(sB2), g_wf_dep + (size_t)blk * 528, tid);
    cp_commit();
    stageA16<128>(sA, g_xn + (size_t)tok0 * DD + blk * 64, DD, tid);
    cp_wait<0>();
    __syncthreads();

    float as_[8][4] = {}, ad_[8][4] = {};
#pragma unroll
    for (int ks = 0; ks < 4; ks++) {
        unsigned a[4];
        *reinterpret_cast<uint4*>(a) =
            *reinterpret_cast<const uint4*>(&sA[(w * 4 + ks) * ASLOT + lane * 4]);
#pragma unroll
        for (int nt = 0; nt < 8; nt++) {
            int off = (nt * 4 + ks) * BSLOT + lane * 2;
            unsigned bb[2];
            *reinterpret_cast<uint2*>(bb) = *reinterpret_cast<const uint2*>(&sB1[off]);
            mma_bf16(as_[nt], a, bb);
            *reinterpret_cast<uint2*>(bb) = *reinterpret_cast<const uint2*>(&sB2[off]);
            mma_bf16(ad_[nt], a, bb);
        }
    }
    __syncthreads();                  // staging dead; alias scan buffers

    float*    sD  = reinterpret_cast<float*>(dyn);           // [128][66] fp32
    unsigned* sHD = dyn + 8448;                              // [128][33] bf16x2
    float*    sS  = reinterpret_cast<float*>(dyn + 12672);   // [4][64]
    float*    sQ  = sS + 256;                                // [4][64]
    float*    sC  = sQ + 256;                                // [64]

    {
        float Kf = (float)(*kptr);
        int g = lane >> 2, t = lane & 3;
        int rl0 = w * 16 + g;
#pragma unroll
        for (int nt = 0; nt < 8; nt++) {
            int nl = nt * 8 + t * 2;
            int gch = blk * 64 + nl;
            float gn0 = gain_of(gch, Kf, lAd, ldtd);
            float gn1 = gain_of(gch + 1, Kf, lAd, ldtd);
            *reinterpret_cast<float2*>(&sD[rl0 * SDS + nl]) =
                make_float2(siluf(as_[nt][0]), siluf(as_[nt][1]));
            *reinterpret_cast<float2*>(&sD[(rl0 + 8) * SDS + nl]) =
                make_float2(siluf(as_[nt][2]), siluf(as_[nt][3]));
            sHD[rl0 * 33 + (nl >> 1)] =
                pk(gn0 * siluf(ad_[nt][0]), gn1 * siluf(ad_[nt][1]));
            sHD[(rl0 + 8) * 33 + (nl >> 1)] =
                pk(gn0 * siluf(ad_[nt][2]), gn1 * siluf(ad_[nt][3]));
        }
    }
    __syncthreads();

    int ch = tid & 63, q = tid >> 6;
    int gch = blk * 64 + ch;
    float a  = decay1(lAs, ldts, gch);
    float la = __logf(a);
    float a32 = __expf(32.0f * la);
    float aT  = __expf(128.0f * la);

    // local quarter scan
    {
        float y = 0.0f;
        int base = q * 32;
#pragma unroll 8
        for (int s = 0; s < 32; s++) {
            float* p = &sD[(base + s) * SDS + ch];
            y = fmaf(a, y, *p);
            *p = y;
        }
        sS[q * 64 + ch] = y;
    }
    __syncthreads();

    // quarter combine + aggregate publish
    float agg = 0.0f;
    if (tid < 64) {
        float C = 0.0f;
#pragma unroll
        for (int q2 = 0; q2 < 4; q2++) {
            sQ[q2 * 64 + tid] = C;
            C = fmaf(C, a32, sS[q2 * 64 + tid]);
        }
        agg = C;
        g_aggv[(size_t)(chain * NPOS + pos) * 64 + tid] = agg;
    }
    __syncthreads();
    if (tid == 0) {
        __threadfence();
        st_rel(&g_state[chain * NPOS + pos], 1);
    }

    // lookback
    if (tid < 64) {
        float carry = 0.0f;
        if (pos > 0) {
            float f = 1.0f;
            int p = pos - 1;
            while (true) {
                int st;
                do { st = ld_acq(&g_state[chain * NPOS + p]); } while (st == 0);
                if (st == 2) {
                    carry = fmaf(f, g_incv[(size_t)(chain * NPOS + p) * 64 + tid], carry);
                    break;
                }
                carry = fmaf(f, g_aggv[(size_t)(chain * NPOS + p) * 64 + tid], carry);
                f *= aT;
                if (--p < 0) break;
            }
        }
        sC[tid] = carry;
        if (pos < NPOS - 1)
            g_incv[(size_t)(chain * NPOS + pos) * 64 + tid] = fmaf(carry, aT, agg);
    }
    __syncthreads();
    if (tid == 0 && pos < NPOS - 1) {
        __threadfence();
        st_rel(&g_state[chain * NPOS + pos], 2);
    }

    // final combine: h = local + eff_carry*a^(s+1) + hd
    {
        float carry = sC[ch];
        float a64 = a32 * a32;
        float aq = (q == 0) ? 1.0f : (q == 1) ? a32 : (q == 2) ? a64 : a64 * a32;
        float eff = fmaf(carry, aq, sQ[q * 64 + ch]);
        float pw = eff * a;
        int base = q * 32;
#pragma unroll 8
        for (int s = 0; s < 32; s++) {
            int row = base + s;
            unsigned hu = sHD[row * 33 + (ch >> 1)];
            float2 hp = __bfloat1622float2(*reinterpret_cast<__nv_bfloat162*>(&hu));
            float hdv = (ch & 1) ? hp.y : hp.x;
            float* p = &sD[row * SDS + ch];
            *p = *p + pw + hdv;
            pw *= a;
        }
    }
    __syncthreads();

    // per-(token, blk) sum-of-squares partials (warp-per-row)
#pragma unroll
    for (int it = 0; it < 16; it++) {
        int row = w + it * 8;
        float2 hv = *reinterpret_cast<const float2*>(&sD[row * SDS + lane * 2]);
        float p = fmaf(hv.x, hv.x, hv.y * hv.y);
#pragma unroll
        for (int off = 16; off > 0; off >>= 1) p += __shfl_xor_sync(0xffffffffu, p, off);
        if (lane == 0) g_ssp[(size_t)(tok0 + row) * 16 + blk] = p;
    }

    // fragment-major store of h -> g_hnf[slab][blk]
    {
        unsigned* dst = (unsigned*)g_hnf + (size_t)(slab * 16 + blk) * ASZ128;
#pragma unroll
        for (int it = 0; it < 4; it++) {
            int idx = tid + it * 256;      // 0..1023
            int slot = idx >> 5;           // 0..31
            int l = idx & 31;
            int mt = slot >> 2, ks = slot & 3;
            int gg = l >> 2, t0 = l & 3;
            int r0w = mt * 16 + gg;
            int k0 = ks * 16 + t0 * 2;
            uint4 o;
            o.x = pk(sD[r0w * SDS + k0],           sD[r0w * SDS + k0 + 1]);
            o.y = pk(sD[(r0w + 8) * SDS + k0],     sD[(r0w + 8) * SDS + k0 + 1]);
            o.z = pk(sD[r0w * SDS + k0 + 8],       sD[r0w * SDS + k0 + 9]);
            o.w = pk(sD[(r0w + 8) * SDS + k0 + 8], sD[(r0w + 8) * SDS + k0 + 9]);
            *reinterpret_cast<uint4*>(dst + slot * ASLOT + l * 4) = o;
        }
    }
}

// ---------------- G2: pipelined hybrid staging with register prefetch ----------------
#define G2SMEM ((2 * ASZ128 + 3 * BSZ) * 4)   // 59136 bytes

__global__ void __launch_bounds__(256) k_g2() {
    extern __shared__ __align__(16) unsigned dsm[];
    unsigned* sA0 = dsm;
    unsigned* sA1 = dsm + ASZ128;
    unsigned* sB0 = dsm + 2 * ASZ128;
    unsigned* sB1 = sB0 + BSZ;
    unsigned* sB2 = sB1 + BSZ;
    int blk = blockIdx.y;
    int slab = blockIdx.x;
    int tok0 = slab * 128;
    int tid = threadIdx.x, lane = tid & 31, w = tid >> 5;
    const uint4* wp = g_wf_post + (size_t)(blk * 3) * 528;
    int gc0 = blk * 3;
    bool hn0 = gc0 < 16, hn1 = gc0 + 1 < 16, hn2 = gc0 + 2 < 16;

    // group0: all B tiles + A0 if frag
    cpcopy<528>(sptr(sB0), wp, tid);
    cpcopy<528>(sptr(sB1), wp + 528, tid);
    cpcopy<528>(sptr(sB2), wp + 1056, tid);
    if (hn0) cpcopy<1056>(sptr(sA0), g_hnf + (size_t)(slab * 16 + gc0) * 1056, tid);
    cp_commit();
    // group1: A1 if frag (possibly empty)
    if (hn1) cpcopy<1056>(sptr(sA1), g_hnf + (size_t)(slab * 16 + gc0 + 1) * 1056, tid);
    cp_commit();

    RowRegs r1, r2;
    if (!hn0) {
        RowRegs r0;
        row_load(r0, tok0, gc0, tid);
        row_sts(sA0, r0, tid);
    }
    if (!hn1) row_load(r1, tok0, gc0 + 1, tid);

    // inline rsh for this thread's two accumulator rows
    int g = lane >> 2, t = lane & 3;
    int r0t = tok0 + w * 16 + g;
    float rsh_a, rsh_b;
    {
        const float4* p = reinterpret_cast<const float4*>(&g_ssp[(size_t)r0t * 16]);
        float4 q0 = p[0], q1 = p[1], q2 = p[2], q3 = p[3];
        float s = q0.x + q0.y + q0.z + q0.w + q1.x + q1.y + q1.z + q1.w
                + q2.x + q2.y + q2.z + q2.w + q3.x + q3.y + q3.z + q3.w;
        rsh_a = rsqrtf(s * (1.0f / DD) + EPSV);
        p = reinterpret_cast<const float4*>(&g_ssp[(size_t)(r0t + 8) * 16]);
        q0 = p[0]; q1 = p[1]; q2 = p[2]; q3 = p[3];
        s = q0.x + q0.y + q0.z + q0.w + q1.x + q1.y + q1.z + q1.w
          + q2.x + q2.y + q2.z + q2.w + q3.x + q3.y + q3.z + q3.w;
        rsh_b = rsqrtf(s * (1.0f / DD) + EPSV);
    }
    int hnc = 16 - gc0;
    hnc = hnc < 0 ? 0 : (hnc > 3 ? 3 : hnc);

    float acc[8][4] = {};
    cp_wait<1>();                 // group0 done (B tiles + A0 frag)
    __syncthreads();
    mma_chunk128(acc, sA0, sB0, w, lane);
    if (hnc == 1) scale_acc(acc, rsh_a, rsh_b);
    __syncthreads();

    // group2: A2 (frag) or empty + register prefetch of row A2
    if (hn2) {
        cpcopy<1056>(sptr(sA0), g_hnf + (size_t)(slab * 16 + gc0 + 2) * 1056, tid);
        cp_commit();
    } else {
        cp_commit();
        row_load(r2, tok0, gc0 + 2, tid);
    }
    if (!hn1) row_sts(sA1, r1, tid);
    cp_wait<1>();                 // groups 0,1 done (A1 frag if any)
    __syncthreads();
    mma_chunk128(acc, sA1, sB1, w, lane);
    if (hnc == 2) scale_acc(acc, rsh_a, rsh_b);
    __syncthreads();

    if (!hn2) row_sts(sA0, r2, tid);
    cp_wait<0>();                 // group2 done
    __syncthreads();
    mma_chunk128(acc, sA0, sB2, w, lane);
    if (hnc == 3) scale_acc(acc, rsh_a, rsh_b);

    unsigned* rf = (unsigned*)g_rf + ((size_t)(slab * 16 + blk)) * ASZ128;
#pragma unroll
    for (int nt = 0; nt < 8; nt++) {
        int ks = nt >> 1, hi = nt & 1;
        unsigned* p = rf + (w * 4 + ks) * ASLOT + (g * 4 + t) * 4 + 2 * hi;
        p[0] = pk(siluf(acc[nt][0]), siluf(acc[nt][1]));
        p[1] = pk(siluf(acc[nt][2]), siluf(acc[nt][3]));
    }
}

// ---------------- G3: t partials, K split in halves ----------------
__device__ __forceinline__ void g3_issue(unsigned dA, unsigned dB, int slab16, int halfoff,
                                         int kt, int tid) {
    cpcopy<528>(dA, g_rf + (size_t)(slab16 + kt) * 1056 + halfoff, tid);
    cpcopy<528>(dB, g_wf_lrB + (size_t)kt * 528, tid);
    cp_commit();
}

__global__ void __launch_bounds__(256) k_g3() {
    __shared__ __align__(16) unsigned smem[2 * ASZ64 + 2 * BSZ];
    unsigned* sAb[2] = { smem, smem + ASZ64 };
    unsigned* sBb[2] = { smem + 2 * ASZ64, smem + 2 * ASZ64 + BSZ };
    int tok0 = blockIdx.x * 64;
    int khalf = blockIdx.y;           // 0/1: k-chunks [0,8) or [8,16)
    int kbase = khalf * 8;
    int tid = threadIdx.x, lane = tid & 31, w = tid >> 5, wm = w & 3, wn = w >> 2;
    int slab16 = (tok0 >> 7) * 16;
    int halfoff = ((tok0 >> 6) & 1) * 528;

    g3_issue(sptr(sAb[0]), sptr(sBb[0]), slab16, halfoff, kbase + 0, tid);
    g3_issue(sptr(sAb[1]), sptr(sBb[1]), slab16, halfoff, kbase + 1, tid);

    float acc[4][4] = {};
#pragma unroll
    for (int kt = 0; kt < 8; kt++) {
        if (kt < 7) cp_wait<1>(); else cp_wait<0>();
        __syncthreads();
        mma_chunk64(acc, sAb[kt & 1], sBb[kt & 1], wm, wn, lane);
        __syncthreads();
        if (kt + 2 < 8)
            g3_issue(sptr(sAb[kt & 1]), sptr(sBb[kt & 1]), slab16, halfoff, kbase + kt + 2, tid);
    }

    int g = lane >> 2, t = lane & 3;
    int mtg = ((tok0 & 64) >> 4) + wm;
    unsigned* tf = (unsigned*)g_tf + (size_t)(khalf * NT128 + (tok0 >> 7)) * ASZ128;
#pragma unroll
    for (int nt = 0; nt < 4; nt++) {
        int ng = wn * 4 + nt;
        int ks = ng >> 1, hi = ng & 1;
        unsigned* p = tf + (mtg * 4 + ks) * ASLOT + (g * 4 + t) * 4 + 2 * hi;
        p[0] = pk(acc[nt][0], acc[nt][1]);
        p[1] = pk(acc[nt][2], acc[nt][3]);
    }
}

// ---------------- G4: out = x + bd(r, w_local) + (t0 + t1) @ lr_A^T ----------------
#define G4SMEM (2 * (ASZ128 + BSZ) * 4)

__global__ void __launch_bounds__(256) k_g4(const float* __restrict__ x,
                                            float* __restrict__ out) {
    extern __shared__ __align__(16) unsigned dsm[];
    unsigned* sA0 = dsm;
    unsigned* sB0 = dsm + ASZ128;
    unsigned* sA1 = dsm + ASZ128 + BSZ;
    unsigned* sB1 = dsm + 2 * ASZ128 + BSZ;
    int blk = blockIdx.y;
    int tok0 = blockIdx.x * 128;
    int slab = tok0 >> 7;
    int tid = threadIdx.x, lane = tid & 31, w = tid >> 5;

    cpcopy<1056>(sptr(sA0), g_rf + (size_t)(slab * 16 + blk) * 1056, tid);
    cpcopy<528>(sptr(sB0), g_wf_loc + (size_t)blk * 528, tid);
    cp_commit();
    cpcopy<1056>(sptr(sA1), g_tf + (size_t)slab * 1056, tid);
    cpcopy<528>(sptr(sB1), g_wf_lrA + (size_t)blk * 528, tid);
    cp_commit();

    float acc[8][4] = {};
    cp_wait<1>();
    __syncthreads();
    mma_chunk128(acc, sA0, sB0, w, lane);
    __syncthreads();
    cpcopy<1056>(sptr(sA0), g_tf + (size_t)(NT128 + slab) * 1056, tid);
    cp_commit();

    cp_wait<1>();
    __syncthreads();
    mma_chunk128(acc, sA1, sB1, w, lane);

    cp_wait<0>();
    __syncthreads();
    mma_chunk128(acc, sA0, sB1, w, lane);

    int g = lane >> 2, t = lane & 3;
    int r0 = tok0 + w * 16 + g;
#pragma unroll
    for (int nt = 0; nt < 8; nt++) {
        int n = blk * 64 + nt * 8 + t * 2;
        size_t i0 = (size_t)r0 * DD + n;
        size_t i1 = (size_t)(r0 + 8) * DD + n;
        float2 x0 = *reinterpret_cast<const float2*>(&x[i0]);
        float2 x1 = *reinterpret_cast<const float2*>(&x[i1]);
        *reinterpret_cast<float2*>(&out[i0]) = make_float2(x0.x + acc[nt][0], x0.y + acc[nt][1]);
        *reinterpret_cast<float2*>(&out[i1]) = make_float2(x1.x + acc[nt][2], x1.y + acc[nt][3]);
    }
}

// ---------------- launch ----------------
extern "C" void kernel_launch(void* const* d_in, const int* in_sizes, int n_in,
                              void* d_out, int out_size) {
    const float* x    = (const float*)d_in[0];
    const int*   actk = (const int*)  d_in[1];
    const float* wseq = (const float*)d_in[2];
    const float* wdep = (const float*)d_in[3];
    const float* wpost= (const float*)d_in[4];
    const float* wloc = (const float*)d_in[5];
    const float* lrA  = (const float*)d_in[6];
    const float* lrB  = (const float*)d_in[7];
    const float* lAs  = (const float*)d_in[8];
    const float* ldts = (const float*)d_in[9];
    const float* lAd  = (const float*)d_in[10];
    const float* ldtd = (const float*)d_in[11];
    float* out = (float*)d_out;

    static bool attr_done = false;
    if (!attr_done) {
        cudaFuncSetAttribute(k_g1s, cudaFuncAttributeMaxDynamicSharedMemorySize, G1SMEM);
        cudaFuncSetAttribute(k_g2,  cudaFuncAttributeMaxDynamicSharedMemorySize, G2SMEM);
        cudaFuncSetAttribute(k_g4,  cudaFuncAttributeMaxDynamicSharedMemorySize, G4SMEM);
        attr_done = true;
    }

    k_prep<<<128 + NTOK / 8, 256>>>(x, wseq, wdep, wloc, lrA, wpost, lrB);
    k_g1s<<<NT128 * 16, 256, G1SMEM>>>(lAd, ldtd, lAs, ldts, actk);
    k_g2<<<dim3(NT128, NBLK), 256, G2SMEM>>>();
    k_g3<<<dim3(NTOK / 64, 2), 256>>>();
    k_g4<<<dim3(NT128, NBLK), 256, G4SMEM>>>(x, out);
}

// round 12
// speedup vs baseline: 1.0541x; 1.0541x over previous
#include <cuda_runtime.h>
#include <cuda_bf16.h>
#include <math.h>

// ---------------- problem constants ----------------
#define BB 4
#define TT_SEQ 4096
#define DD 1024
#define NTOK (BB*TT_SEQ)          // 16384
#define NBLK 16
#define BIP 192
#define RANKR 64
#define NMEM 128
#define EPSV 1.1920929e-07f
#define NT128 (NTOK/128)          // 128
#define NPOS 32                   // 128-token slabs per batch
#define NCHAIN 64                 // (b, blk) chains

// fragment-slot strides
#define ASLOT 132
#define BSLOT 66
#define BSZ (32*BSLOT)            // 2112 uints
#define ASZ64  (16*ASLOT)
#define ASZ128 (32*ASLOT)         // 4224 uints
#define SDS 66

// ---------------- scratch (device globals; no allocation) ----------------
__device__ __nv_bfloat16 g_xn   [NTOK*DD];
__device__ __nv_bfloat16 g_hn   [NTOK*DD];
__device__ float g_rsx  [NTOK];
__device__ float g_rsh  [NTOK];

// decoupled-lookback state
__device__ int   g_ticket;
__device__ int   g_state[NCHAIN*NPOS];
__device__ float g_aggv [NCHAIN*NPOS*64];
__device__ float g_incv [NCHAIN*NPOS*64];

// fragment-major activations
__device__ uint4 g_rf[NT128*16*(ASZ128/4)];
__device__ uint4 g_tf[NT128*(ASZ128/4)];

// pre-fragmented bf16 weights
__device__ uint4 g_wf_seq [NBLK*BSZ/4];
__device__ uint4 g_wf_dep [NBLK*BSZ/4];
__device__ uint4 g_wf_loc [NBLK*BSZ/4];
__device__ uint4 g_wf_lrA [NBLK*BSZ/4];
__device__ uint4 g_wf_post[NBLK*3*BSZ/4];
__device__ uint4 g_wf_lrB [16*BSZ/4];

__device__ __forceinline__ float siluf(float x) {
    return x / (1.0f + __expf(-x));
}

__device__ __forceinline__ unsigned pk(float a, float b) {
    unsigned r;
    asm("cvt.rn.bf16x2.f32 %0, %1, %2;" : "=r"(r) : "f"(b), "f"(a));
    return r;
}

__device__ __forceinline__ float decay1(const float* __restrict__ lA,
                                        const float* __restrict__ ldt, int d) {
    return fmaxf(__expf(-__expf(lA[d]) * __expf(ldt[d])), 1e-6f);
}

// ---------------- acquire/release ----------------
__device__ __forceinline__ int ld_acq(const int* p) {
    int v;
    asm volatile("ld.global.acquire.gpu.b32 %0, [%1];" : "=r"(v) : "l"(p));
    return v;
}
__device__ __forceinline__ void st_rel(int* p, int v) {
    asm volatile("st.global.release.gpu.b32 [%0], %1;" :: "l"(p), "r"(v));
}

// ---------------- cp.async helpers ----------------
__device__ __forceinline__ unsigned sptr(const void* p) {
    return (unsigned)__cvta_generic_to_shared(p);
}
__device__ __forceinline__ void cpa16(unsigned d, const void* s) {
    asm volatile("cp.async.cg.shared.global [%0], [%1], 16;" :: "r"(d), "l"(s));
}
__device__ __forceinline__ void cp_commit() {
    asm volatile("cp.async.commit_group;");
}
template<int N>
__device__ __forceinline__ void cp_wait() {
    asm volatile("cp.async.wait_group %0;" :: "n"(N));
}
template<int N4>
__device__ __forceinline__ void cpcopy(unsigned dsm, const uint4* __restrict__ src, int tid) {
#pragma unroll
    for (int i = tid; i < N4; i += 256) cpa16(dsm + i * 16, src + i);
}

// ---------------- bf16 MMA machinery ----------------
__device__ __forceinline__ void mma_bf16(float c[4], const unsigned a[4], const unsigned b[2]) {
    asm volatile("mma.sync.aligned.m16n8k16.row.col.f32.bf16.bf16.f32 "
        "{%0,%1,%2,%3}, {%4,%5,%6,%7}, {%8,%9}, {%0,%1,%2,%3};"
        : "+f"(c[0]), "+f"(c[1]), "+f"(c[2]), "+f"(c[3])
        : "r"(a[0]), "r"(a[1]), "r"(a[2]), "r"(a[3]), "r"(b[0]), "r"(b[1]));
}

__device__ __forceinline__ void putA16(unsigned* sA, int i, int j0, uint2 u) {
    int mt = i >> 4, rr = i & 15, half = rr >> 3, g = rr & 7;
    int ks = j0 >> 4, kk = j0 & 15, hi = kk >> 3, t0 = (kk & 7) >> 1;
    unsigned* p = &sA[(mt * 4 + ks) * ASLOT + (g * 4 + t0) * 4 + half + 2 * hi];
    p[0] = u.x;
    p[4] = u.y;
}

template<int M>
__device__ __forceinline__ void stageA16(unsigned* sA, const __nv_bfloat16* __restrict__ base,
                                         int rs, int tid) {
#pragma unroll
    for (int it = 0; it < M / 16; ++it) {
        int idx = tid + it * 256;
        int i  = idx >> 4;
        int j0 = (idx & 15) << 2;
        uint2 u = *reinterpret_cast<const uint2*>(base + (size_t)i * rs + j0);
        putA16(sA, i, j0, u);
    }
}

__device__ __forceinline__ void mma_chunk128(float acc[8][4], const unsigned* sA,
                                             const unsigned* sB, int w, int lane) {
#pragma unroll
    for (int ks = 0; ks < 4; ks++) {
        unsigned a[4];
        *reinterpret_cast<uint4*>(a) =
            *reinterpret_cast<const uint4*>(&sA[(w * 4 + ks) * ASLOT + lane * 4]);
#pragma unroll
        for (int nt = 0; nt < 8; nt++) {
            unsigned b[2];
            *reinterpret_cast<uint2*>(b) =
                *reinterpret_cast<const uint2*>(&sB[(nt * 4 + ks) * BSLOT + lane * 2]);
            mma_bf16(acc[nt], a, b);
        }
    }
}

__device__ __forceinline__ void mma_chunk64(float acc[4][4], const unsigned* sA,
                                            const unsigned* sB, int wm, int wn, int lane) {
#pragma unroll
    for (int ks = 0; ks < 4; ks++) {
        unsigned a[4];
        *reinterpret_cast<uint4*>(a) =
            *reinterpret_cast<const uint4*>(&sA[(wm * 4 + ks) * ASLOT + lane * 4]);
#pragma unroll
        for (int nt = 0; nt < 4; nt++) {
            unsigned b[2];
            *reinterpret_cast<uint2*>(b) =
                *reinterpret_cast<const uint2*>(&sB[((wn * 4 + nt) * 4 + ks) * BSLOT + lane * 2]);
            mma_bf16(acc[nt], a, b);
        }
    }
}

__device__ __forceinline__ void scale_acc(float acc[8][4], float ra, float rb) {
#pragma unroll
    for (int nt = 0; nt < 8; nt++) {
        acc[nt][0] *= ra; acc[nt][1] *= ra;
        acc[nt][2] *= rb; acc[nt][3] *= rb;
    }
}

// ---------------- prep: flags + weight fragmentation + x stats ----------------
__global__ void __launch_bounds__(256) k_prep(const float* __restrict__ x,
                                              const float* __restrict__ wseq,
                                              const float* __restrict__ wdep,
                                              const float* __restrict__ wloc,
                                              const float* __restrict__ lrA,
                                              const float* __restrict__ wpost,
                                              const float* __restrict__ lrB) {
    int tid = threadIdx.x;
    if (blockIdx.x == 0) {
        if (tid == 0) g_ticket = 0;
        for (int i = tid; i < NCHAIN * NPOS; i += 256) g_state[i] = 0;
    }
    if (blockIdx.x < 128) {
        int t = blockIdx.x;
        const float* src;
        unsigned* dst;
        int rs;
        if (t < 16)       { src = wseq + (size_t)t * 4096; dst = (unsigned*)g_wf_seq + t * BSZ; rs = 64; }
        else if (t < 32)  { int b = t - 16; src = wdep + (size_t)b * 4096; dst = (unsigned*)g_wf_dep + b * BSZ; rs = 64; }
        else if (t < 48)  { int b = t - 32; src = wloc + (size_t)b * 4096; dst = (unsigned*)g_wf_loc + b * BSZ; rs = 64; }
        else if (t < 64)  { int b = t - 48; src = lrA + (size_t)b * 4096;  dst = (unsigned*)g_wf_lrA + b * BSZ; rs = 64; }
        else if (t < 112) { int i = t - 64; int b = i / 3, kt = i % 3;
                            src = wpost + (size_t)b * 64 * BIP + kt * 64;
                            dst = (unsigned*)g_wf_post + i * BSZ; rs = BIP; }
        else              { int kt = t - 112; src = lrB + kt * 64; dst = (unsigned*)g_wf_lrB + kt * BSZ; rs = DD; }
#pragma unroll
        for (int it = 0; it < 4; ++it) {
            int idx = tid + it * 256;
            int n  = idx >> 4;
            int k0 = (idx & 15) << 2;
            float4 v = *reinterpret_cast<const float4*>(src + (size_t)n * rs + k0);
            int nt = n >> 3, g = n & 7;
            int ks = k0 >> 4, kk = k0 & 15, hi = kk >> 3, t0 = (kk & 7) >> 1;
            unsigned* p = &dst[(nt * 4 + ks) * BSLOT + (g * 4 + t0) * 2 + hi];
            p[0] = pk(v.x, v.y);
            p[2] = pk(v.z, v.w);
        }
    } else {
        int w = tid >> 5, lane = tid & 31;
        int tok = (blockIdx.x - 128) * 8 + w;
        const float4* xr = reinterpret_cast<const float4*>(x + (size_t)tok * DD);
        float4 v[8];
        float ss = 0.0f;
#pragma unroll
        for (int i = 0; i < 8; i++) {
            v[i] = xr[lane + i * 32];
            ss += v[i].x * v[i].x + v[i].y * v[i].y + v[i].z * v[i].z + v[i].w * v[i].w;
        }
#pragma unroll
        for (int off = 16; off > 0; off >>= 1) ss += __shfl_xor_sync(0xffffffffu, ss, off);
        ss = __shfl_sync(0xffffffffu, ss, 0);
        float sc = rsqrtf(ss * (1.0f / DD) + EPSV);
        if (lane == 0) g_rsx[tok] = sc;
        uint2* xo = reinterpret_cast<uint2*>(g_xn + (size_t)tok * DD);
#pragma unroll
        for (int i = 0; i < 8; i++) {
            uint2 o;
            o.x = pk(v[i].x * sc, v[i].y * sc);
            o.y = pk(v[i].z * sc, v[i].w * sc);
            xo[lane + i * 32] = o;
        }
    }
}

// ---------------- gain helper ----------------
__device__ __forceinline__ float gain_of(int gch, float Kf, const float* __restrict__ lAd,
                                         const float* __restrict__ ldtd) {
    if (gch < NMEM) return Kf;
    float a1 = __expf(-__expf(lAd[gch - NMEM]) * __expf(ldtd[gch - NMEM]));
    float om = 1.0f - a1;
    if (fabsf(om) < 1e-6f) return Kf;
    return (1.0f - __expf(Kf * __logf(a1))) / fmaxf(om, 1e-8f);
}

// ---------------- G1S: GEMMs + single-pass scan (decoupled lookback) -> g_hn ----------------
#define G1SMEM (13248 * 4)

__global__ void __launch_bounds__(256) k_g1s(const float* __restrict__ lAd,
                                             const float* __restrict__ ldtd,
                                             const float* __restrict__ lAs,
                                             const float* __restrict__ ldts,
                                             const int* __restrict__ kptr) {
    extern __shared__ __align__(16) unsigned dyn[];
    __shared__ int s_ticket;
    int tid = threadIdx.x, lane = tid & 31, w = tid >> 5;

    if (tid == 0) s_ticket = atomicAdd(&g_ticket, 1);
    __syncthreads();
    int ticket = s_ticket;
    int chain = ticket & (NCHAIN - 1);
    int pos   = ticket >> 6;
    int b = chain >> 4, blk = chain & 15;
    int tok0 = (b * NPOS + pos) * 128;

    unsigned* sA  = dyn;
    unsigned* sB1 = dyn + ASZ128;
    unsigned* sB2 = dyn + ASZ128 + BSZ;

    cpcopy<528>(sptr(sB1), g_wf_seq + (size_t)blk * 528, tid);
    cpcopy<528>(sptr(sB2), g_wf_dep + (size_t)blk * 528, tid);
    cp_commit();
    stageA16<128>(sA, g_xn + (size_t)tok0 * DD + blk * 64, DD, tid);
    cp_wait<0>();
    __syncthreads();

    float as_[8][4] = {}, ad_[8][4] = {};
#pragma unroll
    for (int ks = 0; ks < 4; ks++) {
        unsigned a[4];
        *reinterpret_cast<uint4*>(a) =
            *reinterpret_cast<const uint4*>(&sA[(w * 4 + ks) * ASLOT + lane * 4]);
#pragma unroll
        for (int nt = 0; nt < 8; nt++) {
            int off = (nt * 4 + ks) * BSLOT + lane * 2;
            unsigned bb[2];
            *reinterpret_cast<uint2*>(bb) = *reinterpret_cast<const uint2*>(&sB1[off]);
            mma_bf16(as_[nt], a, bb);
            *reinterpret_cast<uint2*>(bb) = *reinterpret_cast<const uint2*>(&sB2[off]);
            mma_bf16(ad_[nt], a, bb);
        }
    }
    __syncthreads();                  // staging dead; alias scan buffers

    float*    sD  = reinterpret_cast<float*>(dyn);           // [128][66] fp32
    unsigned* sHD = dyn + 8448;                              // [128][33] bf16x2
    float*    sS  = reinterpret_cast<float*>(dyn + 12672);   // [4][64]
    float*    sQ  = sS + 256;                                // [4][64]
    float*    sC  = sQ + 256;                                // [64]

    // epilogue: silu -> drive (fp32, smem) ; gain*silu -> hd (bf16x2, smem)
    {
        float Kf = (float)(*kptr);
        int g = lane >> 2, t = lane & 3;
        int rl0 = w * 16 + g;
#pragma unroll
        for (int nt = 0; nt < 8; nt++) {
            int nl = nt * 8 + t * 2;
            int gch = blk * 64 + nl;
            float gn0 = gain_of(gch, Kf, lAd, ldtd);
            float gn1 = gain_of(gch + 1, Kf, lAd, ldtd);
            *reinterpret_cast<float2*>(&sD[rl0 * SDS + nl]) =
                make_float2(siluf(as_[nt][0]), siluf(as_[nt][1]));
            *reinterpret_cast<float2*>(&sD[(rl0 + 8) * SDS + nl]) =
                make_float2(siluf(as_[nt][2]), siluf(as_[nt][3]));
            sHD[rl0 * 33 + (nl >> 1)] =
                pk(gn0 * siluf(ad_[nt][0]), gn1 * siluf(ad_[nt][1]));
            sHD[(rl0 + 8) * 33 + (nl >> 1)] =
                pk(gn0 * siluf(ad_[nt][2]), gn1 * siluf(ad_[nt][3]));
        }
    }
    __syncthreads();

    // scan thread mapping: ch = tid & 63 (two warps per quarter), q = tid >> 6
    int ch = tid & 63, q = tid >> 6;
    int gch = blk * 64 + ch;
    float a  = decay1(lAs, ldts, gch);
    float la = __logf(a);
    float a32 = __expf(32.0f * la);
    float aT  = __expf(128.0f * la);

    // local quarter scan (in place): sD <- quarter-local inclusive
    {
        float y = 0.0f;
        int base = q * 32;
#pragma unroll 8
        for (int s = 0; s < 32; s++) {
            float* p = &sD[(base + s) * SDS + ch];
            y = fmaf(a, y, *p);
            *p = y;
        }
        sS[q * 64 + ch] = y;
    }
    __syncthreads();

    // quarter combine + aggregate publish
    float agg = 0.0f;
    if (tid < 64) {
        float C = 0.0f;
#pragma unroll
        for (int q2 = 0; q2 < 4; q2++) {
            sQ[q2 * 64 + tid] = C;
            C = fmaf(C, a32, sS[q2 * 64 + tid]);
        }
        agg = C;
        g_aggv[(size_t)(chain * NPOS + pos) * 64 + tid] = agg;
    }
    __syncthreads();
    if (tid == 0) {
        __threadfence();
        st_rel(&g_state[chain * NPOS + pos], 1);
    }

    // lookback
    if (tid < 64) {
        float carry = 0.0f;
        if (pos > 0) {
            float f = 1.0f;
            int p = pos - 1;
            while (true) {
                int st;
                do { st = ld_acq(&g_state[chain * NPOS + p]); } while (st == 0);
                if (st == 2) {
                    carry = fmaf(f, g_incv[(size_t)(chain * NPOS + p) * 64 + tid], carry);
                    break;
                }
                carry = fmaf(f, g_aggv[(size_t)(chain * NPOS + p) * 64 + tid], carry);
                f *= aT;
                if (--p < 0) break;
            }
        }
        sC[tid] = carry;
        if (pos < NPOS - 1)
            g_incv[(size_t)(chain * NPOS + pos) * 64 + tid] = fmaf(carry, aT, agg);
    }
    __syncthreads();
    if (tid == 0 && pos < NPOS - 1) {
        __threadfence();
        st_rel(&g_state[chain * NPOS + pos], 2);
    }

    // final combine: h = local + eff_carry * a^(s+1) + hd   (in place into sD)
    {
        float carry = sC[ch];
        float a64 = a32 * a32;
        float aq = (q == 0) ? 1.0f : (q == 1) ? a32 : (q == 2) ? a64 : a64 * a32;
        float eff = fmaf(carry, aq, sQ[q * 64 + ch]);
        float pw = eff * a;
        int base = q * 32;
#pragma unroll 8
        for (int s = 0; s < 32; s++) {
            int row = base + s;
            unsigned hu = sHD[row * 33 + (ch >> 1)];
            float2 hp = __bfloat1622float2(*reinterpret_cast<__nv_bfloat162*>(&hu));
            float hdv = (ch & 1) ? hp.y : hp.x;
            float* p = &sD[row * SDS + ch];
            *p = *p + pw + hdv;
            pw *= a;
        }
    }
    __syncthreads();

    // pack + coalesced store of h -> g_hn
#pragma unroll
    for (int it = 0; it < 16; it++) {
        int idx = tid + it * 256;        // 4096 = 128 rows x 32 uint pairs
        int row = idx >> 5;
        int c2  = idx & 31;
        float h0 = sD[row * SDS + c2 * 2];
        float h1 = sD[row * SDS + c2 * 2 + 1];
        *reinterpret_cast<unsigned*>(&g_hn[(size_t)(tok0 + row) * DD + blk * 64 + c2 * 2]) =
            pk(h0, h1);
    }
}

// ---------------- rstd: warp-per-token over g_hn -> g_rsh ----------------
__global__ void __launch_bounds__(256) k_rstd() {
    int w = threadIdx.x >> 5, lane = threadIdx.x & 31;
    int tok = blockIdx.x * 8 + w;
    const uint4* hr = reinterpret_cast<const uint4*>(g_hn + (size_t)tok * DD);
    float ss = 0.0f;
#pragma unroll
    for (int i = 0; i < 4; i++) {
        uint4 u = hr[lane + i * 32];
        float2 a0 = __bfloat1622float2(*reinterpret_cast<__nv_bfloat162*>(&u.x));
        float2 a1 = __bfloat1622float2(*reinterpret_cast<__nv_bfloat162*>(&u.y));
        float2 a2 = __bfloat1622float2(*reinterpret_cast<__nv_bfloat162*>(&u.z));
        float2 a3 = __bfloat1622float2(*reinterpret_cast<__nv_bfloat162*>(&u.w));
        ss += a0.x * a0.x + a0.y * a0.y + a1.x * a1.x + a1.y * a1.y
            + a2.x * a2.x + a2.y * a2.y + a3.x * a3.x + a3.y * a3.y;
    }
#pragma unroll
    for (int off = 16; off > 0; off >>= 1) ss += __shfl_xor_sync(0xffffffffu, ss, off);
    if (lane == 0) g_rsh[tok] = rsqrtf(ss * (1.0f / DD) + EPSV);
}

// ---------------- G2 helpers: concat A prefetch (PASSTHROUGH — no scaling) ----------------
struct CatRegs { uint2 u[8]; };

__device__ __forceinline__ void catA_load(CatRegs& r, int tok0, int gcat0, int tid) {
#pragma unroll
    for (int it = 0; it < 8; ++it) {
        int idx = tid + it * 256;
        int i  = idx >> 4;
        int j0 = (idx & 15) << 2;
        int gcat = gcat0 + j0;
        int tok = tok0 + i;
        uint2 u;
        if (gcat < 1024) {
            u = *reinterpret_cast<const uint2*>(&g_hn[(size_t)tok * DD + gcat]);
        } else if (gcat < 2048) {
            u = *reinterpret_cast<const uint2*>(&g_xn[(size_t)tok * DD + (gcat - 1024)]);
        } else {
            if ((tok & (TT_SEQ - 1)) == 0) { u.x = 0u; u.y = 0u; }
            else u = *reinterpret_cast<const uint2*>(&g_xn[(size_t)(tok - 1) * DD + (gcat - 2048)]);
        }
        r.u[it] = u;
    }
}

__device__ __forceinline__ void catA_sts(unsigned* sA, const CatRegs& r, int tid) {
#pragma unroll
    for (int it = 0; it < 8; ++it) {
        int idx = tid + it * 256;
        putA16(sA, idx >> 4, (idx & 15) << 2, r.u[it]);
    }
}

// ---------------- G2: r = silu(bd(concat, w_post)), rsh applied on accumulator ----------------
__global__ void __launch_bounds__(256) k_g2() {
    __shared__ __align__(16) unsigned sA[ASZ128];
    __shared__ __align__(16) unsigned sB[2][BSZ];
    int blk = blockIdx.y;
    int tok0 = blockIdx.x * 128;
    int tid = threadIdx.x, lane = tid & 31, w = tid >> 5;
    const uint4* wp = g_wf_post + (size_t)(blk * 3) * 528;

    cpcopy<528>(sptr(sB[0]), wp, tid);       cp_commit();
    cpcopy<528>(sptr(sB[1]), wp + 528, tid); cp_commit();

    CatRegs r;
    catA_load(r, tok0, blk * BIP, tid);
    catA_sts(sA, r, tid);
    cp_wait<1>();
    __syncthreads();

    // rsh factors for this thread's two accumulator rows (chunk-aligned factorization)
    int g = lane >> 2, t = lane & 3;
    int r0 = tok0 + w * 16 + g;
    float rsh_a = g_rsh[r0];
    float rsh_b = g_rsh[r0 + 8];
    int hnc = 16 - blk * 3;                 // # of pure-hn chunks among kt=0..2
    hnc = hnc < 0 ? 0 : (hnc > 3 ? 3 : hnc);

    float acc[8][4] = {};
    // kt = 0
    catA_load(r, tok0, blk * BIP + 64, tid);
    mma_chunk128(acc, sA, sB[0], w, lane);
    if (hnc == 1) scale_acc(acc, rsh_a, rsh_b);
    __syncthreads();
    cpcopy<528>(sptr(sB[0]), wp + 1056, tid); cp_commit();
    catA_sts(sA, r, tid);
    cp_wait<1>();
    __syncthreads();
    // kt = 1
    catA_load(r, tok0, blk * BIP + 128, tid);
    mma_chunk128(acc, sA, sB[1], w, lane);
    if (hnc == 2) scale_acc(acc, rsh_a, rsh_b);
    __syncthreads();
    catA_sts(sA, r, tid);
    cp_wait<0>();
    __syncthreads();
    // kt = 2
    mma_chunk128(acc, sA, sB[0], w, lane);
    if (hnc == 3) scale_acc(acc, rsh_a, rsh_b);

    // epilogue -> g_rf (fragment layout, slab (tok0/128, blk))
    unsigned* rf = (unsigned*)g_rf + ((size_t)((tok0 >> 7) * 16 + blk)) * ASZ128;
#pragma unroll
    for (int nt = 0; nt < 8; nt++) {
        int ks = nt >> 1, hi = nt & 1;
        unsigned* p = rf + (w * 4 + ks) * ASLOT + (g * 4 + t) * 4 + 2 * hi;
        p[0] = pk(siluf(acc[nt][0]), siluf(acc[nt][1]));
        p[1] = pk(siluf(acc[nt][2]), siluf(acc[nt][3]));
    }
}

// ---------------- G3: t = r @ lr_B^T (M=64, 2-stage cp.async pipeline) ----------------
__device__ __forceinline__ void g3_issue(unsigned dA, unsigned dB, int slab16, int halfoff,
                                         int kt, int tid) {
    cpcopy<528>(dA, g_rf + (size_t)(slab16 + kt) * 1056 + halfoff, tid);
    cpcopy<528>(dB, g_wf_lrB + (size_t)kt * 528, tid);
    cp_commit();
}

__global__ void __launch_bounds__(256) k_g3() {
    __shared__ __align__(16) unsigned smem[2 * ASZ64 + 2 * BSZ];
    unsigned* sAb[2] = { smem, smem + ASZ64 };
    unsigned* sBb[2] = { smem + 2 * ASZ64, smem + 2 * ASZ64 + BSZ };
    int tok0 = blockIdx.x * 64;
    int tid = threadIdx.x, lane = tid & 31, w = tid >> 5, wm = w & 3, wn = w >> 2;
    int slab16 = (tok0 >> 7) * 16;
    int halfoff = ((tok0 >> 6) & 1) * 528;

    g3_issue(sptr(sAb[0]), sptr(sBb[0]), slab16, halfoff, 0, tid);
    g3_issue(sptr(sAb[1]), sptr(sBb[1]), slab16, halfoff, 1, tid);

    float acc[4][4] = {};
#pragma unroll
    for (int kt = 0; kt < 16; kt++) {
        if (kt < 15) cp_wait<1>(); else cp_wait<0>();
        __syncthreads();
        mma_chunk64(acc, sAb[kt & 1], sBb[kt & 1], wm, wn, lane);
        __syncthreads();
        if (kt + 2 < 16)
            g3_issue(sptr(sAb[kt & 1]), sptr(sBb[kt & 1]), slab16, halfoff, kt + 2, tid);
    }

    // epilogue -> g_tf fragment layout
    int g = lane >> 2, t = lane & 3;
    int mtg = ((tok0 & 64) >> 4) + wm;
    unsigned* tf = (unsigned*)g_tf + (size_t)(tok0 >> 7) * ASZ128;
#pragma unroll
    for (int nt = 0; nt < 4; nt++) {
        int ng = wn * 4 + nt;
        int ks = ng >> 1, hi = ng & 1;
        unsigned* p = tf + (mtg * 4 + ks) * ASLOT + (g * 4 + t) * 4 + 2 * hi;
        p[0] = pk(acc[nt][0], acc[nt][1]);
        p[1] = pk(acc[nt][2], acc[nt][3]);
    }
}

// ---------------- G4: out = x + bd(r, w_local) + t @ lr_A^T (M=128) ----------------
#define G4SMEM (2 * (ASZ128 + BSZ) * 4)

__global__ void __launch_bounds__(256) k_g4(const float* __restrict__ x,
                                            float* __restrict__ out) {
    extern __shared__ __align__(16) unsigned dsm[];
    unsigned* sA0 = dsm;
    unsigned* sB0 = dsm + ASZ128;
    unsigned* sA1 = dsm + ASZ128 + BSZ;
    unsigned* sB1 = dsm + 2 * ASZ128 + BSZ;
    int blk = blockIdx.y;
    int tok0 = blockIdx.x * 128;
    int tid = threadIdx.x, lane = tid & 31, w = tid >> 5;
    int slab16 = (tok0 >> 7) * 16;

    cpcopy<1056>(sptr(sA0), g_rf + (size_t)(slab16 + blk) * 1056, tid);
    cpcopy<528>(sptr(sB0), g_wf_loc + (size_t)blk * 528, tid);
    cp_commit();
    cpcopy<1056>(sptr(sA1), g_tf + (size_t)(tok0 >> 7) * 1056, tid);
    cpcopy<528>(sptr(sB1), g_wf_lrA + (size_t)blk * 528, tid);
    cp_commit();

    float acc[8][4] = {};
    cp_wait<1>();
    __syncthreads();
    mma_chunk128(acc, sA0, sB0, w, lane);
    cp_wait<0>();
    __syncthreads();
    mma_chunk128(acc, sA1, sB1, w, lane);

    int g = lane >> 2, t = lane & 3;
    int r0 = tok0 + w * 16 + g;
#pragma unroll
    for (int nt = 0; nt < 8; nt++) {
        int n = blk * 64 + nt * 8 + t * 2;
        size_t i0 = (size_t)r0 * DD + n;
        size_t i1 = (size_t)(r0 + 8) * DD + n;
        float2 x0 = *reinterpret_cast<const float2*>(&x[i0]);
        float2 x1 = *reinterpret_cast<const float2*>(&x[i1]);
        *reinterpret_cast<float2*>(&out[i0]) = make_float2(x0.x + acc[nt][0], x0.y + acc[nt][1]);
        *reinterpret_cast<float2*>(&out[i1]) = make_float2(x1.x + acc[nt][2], x1.y + acc[nt][3]);
    }
}

// ---------------- launch ----------------
extern "C" void kernel_launch(void* const* d_in, const int* in_sizes, int n_in,
                              void* d_out, int out_size) {
    const float* x    = (const float*)d_in[0];
    const int*   actk = (const int*)  d_in[1];
    const float* wseq = (const float*)d_in[2];
    const float* wdep = (const float*)d_in[3];
    const float* wpost= (const float*)d_in[4];
    const float* wloc = (const float*)d_in[5];
    const float* lrA  = (const float*)d_in[6];
    const float* lrB  = (const float*)d_in[7];
    const float* lAs  = (const float*)d_in[8];
    const float* ldts = (const float*)d_in[9];
    const float* lAd  = (const float*)d_in[10];
    const float* ldtd = (const float*)d_in[11];
    float* out = (float*)d_out;

    static bool attr_done = false;
    if (!attr_done) {
        cudaFuncSetAttribute(k_g4, cudaFuncAttributeMaxDynamicSharedMemorySize, G4SMEM);
        cudaFuncSetAttribute(k_g1s, cudaFuncAttributeMaxDynamicSharedMemorySize, G1SMEM);
        attr_done = true;
    }

    dim3 gGemm(NTOK / 128, NBLK);    // (128, 16)

    k_prep<<<128 + NTOK / 8, 256>>>(x, wseq, wdep, wloc, lrA, wpost, lrB);
    k_g1s<<<NT128 * 16, 256, G1SMEM>>>(lAd, ldtd, lAs, ldts, actk);
    k_rstd<<<NTOK / 8, 256>>>();
    k_g2<<<gGemm, 256>>>();
    k_g3<<<NTOK / 64, 256>>>();
    k_g4<<<gGemm, 256, G4SMEM>>>(x, out);
}

// round 13
// speedup vs baseline: 1.1305x; 1.0726x over previous
#include <cuda_runtime.h>
#include <cuda_bf16.h>
#include <math.h>

// ---------------- problem constants ----------------
#define BB 4
#define TT_SEQ 4096
#define DD 1024
#define NTOK (BB*TT_SEQ)          // 16384
#define NBLK 16
#define BIP 192
#define RANKR 64
#define NMEM 128
#define EPSV 1.1920929e-07f
#define NT128 (NTOK/128)          // 128
#define NPOS 32
#define NCHAIN 64

// fragment-slot strides (B tiles and rf/tf activations)
#define ASLOT 132
#define BSLOT 66
#define BSZ (32*BSLOT)            // 2112 uints
#define ASZ64  (16*ASLOT)
#define ASZ128 (32*ASLOT)         // 4224 uints
#define ARSZ 4096                 // row-major A tile: 128 rows x 128B = 4096 uints
#define SDS 66

// ---------------- scratch (device globals; no allocation) ----------------
__device__ __nv_bfloat16 g_xn   [NTOK*DD];
__device__ __nv_bfloat16 g_hn   [NTOK*DD];
__device__ float g_rsx  [NTOK];
__device__ float g_rsh  [NTOK];

// decoupled-lookback state
__device__ int   g_ticket;
__device__ int   g_state[NCHAIN*NPOS];
__device__ float g_aggv [NCHAIN*NPOS*64];
__device__ float g_incv [NCHAIN*NPOS*64];

// fragment-major activations
__device__ uint4 g_rf[NT128*16*(ASZ128/4)];
__device__ uint4 g_tf[NT128*(ASZ128/4)];

// pre-fragmented bf16 weights
__device__ uint4 g_wf_seq [NBLK*BSZ/4];
__device__ uint4 g_wf_dep [NBLK*BSZ/4];
__device__ uint4 g_wf_loc [NBLK*BSZ/4];
__device__ uint4 g_wf_lrA [NBLK*BSZ/4];
__device__ uint4 g_wf_post[NBLK*3*BSZ/4];
__device__ uint4 g_wf_lrB [16*BSZ/4];

__device__ __forceinline__ float siluf(float x) {
    return x / (1.0f + __expf(-x));
}

__device__ __forceinline__ unsigned pk(float a, float b) {
    unsigned r;
    asm("cvt.rn.bf16x2.f32 %0, %1, %2;" : "=r"(r) : "f"(b), "f"(a));
    return r;
}

__device__ __forceinline__ float decay1(const float* __restrict__ lA,
                                        const float* __restrict__ ldt, int d) {
    return fmaxf(__expf(-__expf(lA[d]) * __expf(ldt[d])), 1e-6f);
}

// ---------------- acquire/release ----------------
__device__ __forceinline__ int ld_acq(const int* p) {
    int v;
    asm volatile("ld.global.acquire.gpu.b32 %0, [%1];" : "=r"(v) : "l"(p));
    return v;
}
__device__ __forceinline__ void st_rel(int* p, int v) {
    asm volatile("st.global.release.gpu.b32 [%0], %1;" :: "l"(p), "r"(v));
}

// ---------------- cp.async helpers ----------------
__device__ __forceinline__ unsigned sptr(const void* p) {
    return (unsigned)__cvta_generic_to_shared(p);
}
__device__ __forceinline__ void cpa16(unsigned d, const void* s) {
    asm volatile("cp.async.cg.shared.global [%0], [%1], 16;" :: "r"(d), "l"(s));
}
__device__ __forceinline__ void cpa16z(unsigned d, const void* s) {
    // src-size 0: no bytes read, 16B zero-filled
    asm volatile("cp.async.cg.shared.global [%0], [%1], 16, 0;" :: "r"(d), "l"(s));
}
__device__ __forceinline__ void cp_commit() {
    asm volatile("cp.async.commit_group;");
}
template<int N>
__device__ __forceinline__ void cp_wait() {
    asm volatile("cp.async.wait_group %0;" :: "n"(N));
}
template<int N4>
__device__ __forceinline__ void cpcopy(unsigned dsm, const uint4* __restrict__ src, int tid) {
#pragma unroll
    for (int i = tid; i < N4; i += 256) cpa16(dsm + i * 16, src + i);
}

// row-major A chunk copy: 128 tokens x 64 bf16 (128B/row), SW128 swizzle.
// colbase = tensor + channel_offset ; row token = tok0 + row (minus 1 if SHIFT).
template<bool SHIFT>
__device__ __forceinline__ void cpA_row(unsigned dsm, const __nv_bfloat16* __restrict__ colbase,
                                        int tok0, int tid) {
#pragma unroll
    for (int it = 0; it < 4; ++it) {
        int idx = tid + it * 256;     // 0..1023
        int row = idx >> 3;
        int c16 = idx & 7;
        unsigned dst = dsm + row * 128 + ((c16 ^ (row & 7)) << 4);
        int tok = tok0 + row;
        if (SHIFT) {
            if ((tok & (TT_SEQ - 1)) == 0) cpa16z(dst, colbase);
            else cpa16(dst, colbase + (size_t)(tok - 1) * DD + c16 * 8);
        } else {
            cpa16(dst, colbase + (size_t)tok * DD + c16 * 8);
        }
    }
}

// ---------------- bf16 MMA machinery ----------------
__device__ __forceinline__ void mma_bf16(float c[4], const unsigned a[4], const unsigned b[2]) {
    asm volatile("mma.sync.aligned.m16n8k16.row.col.f32.bf16.bf16.f32 "
        "{%0,%1,%2,%3}, {%4,%5,%6,%7}, {%8,%9}, {%0,%1,%2,%3};"
        : "+f"(c[0]), "+f"(c[1]), "+f"(c[2]), "+f"(c[3])
        : "r"(a[0]), "r"(a[1]), "r"(a[2]), "r"(a[3]), "r"(b[0]), "r"(b[1]));
}

// ldmatrix x4: A fragment (m16 tile mt, k-chunk ks) from swizzled row-major tile
__device__ __forceinline__ void ldsmA(unsigned a[4], unsigned sAbase, int mt, int ks, int lane) {
    int row = mt * 16 + (lane & 7) + ((lane & 8) ? 8 : 0);
    int ci  = ks * 2 + ((lane & 16) ? 1 : 0);
    unsigned addr = sAbase + row * 128 + ((ci ^ (row & 7)) << 4);
    asm volatile("ldmatrix.sync.aligned.m8n8.x4.shared.b16 {%0,%1,%2,%3}, [%4];"
        : "=r"(a[0]), "=r"(a[1]), "=r"(a[2]), "=r"(a[3]) : "r"(addr));
}

// M=128 mma over row-major A (ldmatrix) and fragment-major B
__device__ __forceinline__ void mma_chunk128_lm(float acc[8][4], unsigned sAbase,
                                                const unsigned* sB, int w, int lane) {
#pragma unroll
    for (int ks = 0; ks < 4; ks++) {
        unsigned a[4];
        ldsmA(a, sAbase, w, ks, lane);
#pragma unroll
        for (int nt = 0; nt < 8; nt++) {
            unsigned b[2];
            *reinterpret_cast<uint2*>(b) =
                *reinterpret_cast<const uint2*>(&sB[(nt * 4 + ks) * BSLOT + lane * 2]);
            mma_bf16(acc[nt], a, b);
        }
    }
}

// M=64 fragment-major mma (g3/g4 path, unchanged)
__device__ __forceinline__ void mma_chunk64(float acc[4][4], const unsigned* sA,
                                            const unsigned* sB, int wm, int wn, int lane) {
#pragma unroll
    for (int ks = 0; ks < 4; ks++) {
        unsigned a[4];
        *reinterpret_cast<uint4*>(a) =
            *reinterpret_cast<const uint4*>(&sA[(wm * 4 + ks) * ASLOT + lane * 4]);
#pragma unroll
        for (int nt = 0; nt < 4; nt++) {
            unsigned b[2];
            *reinterpret_cast<uint2*>(b) =
                *reinterpret_cast<const uint2*>(&sB[((wn * 4 + nt) * 4 + ks) * BSLOT + lane * 2]);
            mma_bf16(acc[nt], a, b);
        }
    }
}

__device__ __forceinline__ void mma_chunk128_frag(float acc[8][4], const unsigned* sA,
                                                  const unsigned* sB, int w, int lane) {
#pragma unroll
    for (int ks = 0; ks < 4; ks++) {
        unsigned a[4];
        *reinterpret_cast<uint4*>(a) =
            *reinterpret_cast<const uint4*>(&sA[(w * 4 + ks) * ASLOT + lane * 4]);
#pragma unroll
        for (int nt = 0; nt < 8; nt++) {
            unsigned b[2];
            *reinterpret_cast<uint2*>(b) =
                *reinterpret_cast<const uint2*>(&sB[(nt * 4 + ks) * BSLOT + lane * 2]);
            mma_bf16(acc[nt], a, b);
        }
    }
}

__device__ __forceinline__ void scale_acc(float acc[8][4], float ra, float rb) {
#pragma unroll
    for (int nt = 0; nt < 8; nt++) {
        acc[nt][0] *= ra; acc[nt][1] *= ra;
        acc[nt][2] *= rb; acc[nt][3] *= rb;
    }
}

// ---------------- prep: flags + weight fragmentation + x stats ----------------
__global__ void __launch_bounds__(256) k_prep(const float* __restrict__ x,
                                              const float* __restrict__ wseq,
                                              const float* __restrict__ wdep,
                                              const float* __restrict__ wloc,
                                              const float* __restrict__ lrA,
                                              const float* __restrict__ wpost,
                                              const float* __restrict__ lrB) {
    int tid = threadIdx.x;
    if (blockIdx.x == 0) {
        if (tid == 0) g_ticket = 0;
        for (int i = tid; i < NCHAIN * NPOS; i += 256) g_state[i] = 0;
    }
    if (blockIdx.x < 128) {
        int t = blockIdx.x;
        const float* src;
        unsigned* dst;
        int rs;
        if (t < 16)       { src = wseq + (size_t)t * 4096; dst = (unsigned*)g_wf_seq + t * BSZ; rs = 64; }
        else if (t < 32)  { int b = t - 16; src = wdep + (size_t)b * 4096; dst = (unsigned*)g_wf_dep + b * BSZ; rs = 64; }
        else if (t < 48)  { int b = t - 32; src = wloc + (size_t)b * 4096; dst = (unsigned*)g_wf_loc + b * BSZ; rs = 64; }
        else if (t < 64)  { int b = t - 48; src = lrA + (size_t)b * 4096;  dst = (unsigned*)g_wf_lrA + b * BSZ; rs = 64; }
        else if (t < 112) { int i = t - 64; int b = i / 3, kt = i % 3;
                            src = wpost + (size_t)b * 64 * BIP + kt * 64;
                            dst = (unsigned*)g_wf_post + i * BSZ; rs = BIP; }
        else              { int kt = t - 112; src = lrB + kt * 64; dst = (unsigned*)g_wf_lrB + kt * BSZ; rs = DD; }
#pragma unroll
        for (int it = 0; it < 4; ++it) {
            int idx = tid + it * 256;
            int n  = idx >> 4;
            int k0 = (idx & 15) << 2;
            float4 v = *reinterpret_cast<const float4*>(src + (size_t)n * rs + k0);
            int nt = n >> 3, g = n & 7;
            int ks = k0 >> 4, kk = k0 & 15, hi = kk >> 3, t0 = (kk & 7) >> 1;
            unsigned* p = &dst[(nt * 4 + ks) * BSLOT + (g * 4 + t0) * 2 + hi];
            p[0] = pk(v.x, v.y);
            p[2] = pk(v.z, v.w);
        }
    } else {
        int w = tid >> 5, lane = tid & 31;
        int tok = (blockIdx.x - 128) * 8 + w;
        const float4* xr = reinterpret_cast<const float4*>(x + (size_t)tok * DD);
        float4 v[8];
        float ss = 0.0f;
#pragma unroll
        for (int i = 0; i < 8; i++) {
            v[i] = xr[lane + i * 32];
            ss += v[i].x * v[i].x + v[i].y * v[i].y + v[i].z * v[i].z + v[i].w * v[i].w;
        }
#pragma unroll
        for (int off = 16; off > 0; off >>= 1) ss += __shfl_xor_sync(0xffffffffu, ss, off);
        ss = __shfl_sync(0xffffffffu, ss, 0);
        float sc = rsqrtf(ss * (1.0f / DD) + EPSV);
        if (lane == 0) g_rsx[tok] = sc;
        uint2* xo = reinterpret_cast<uint2*>(g_xn + (size_t)tok * DD);
#pragma unroll
        for (int i = 0; i < 8; i++) {
            uint2 o;
            o.x = pk(v[i].x * sc, v[i].y * sc);
            o.y = pk(v[i].z * sc, v[i].w * sc);
            xo[lane + i * 32] = o;
        }
    }
}

// ---------------- gain helper ----------------
__device__ __forceinline__ float gain_of(int gch, float Kf, const float* __restrict__ lAd,
                                         const float* __restrict__ ldtd) {
    if (gch < NMEM) return Kf;
    float a1 = __expf(-__expf(lAd[gch - NMEM]) * __expf(ldtd[gch - NMEM]));
    float om = 1.0f - a1;
    if (fabsf(om) < 1e-6f) return Kf;
    return (1.0f - __expf(Kf * __logf(a1))) / fmaxf(om, 1e-8f);
}

// ---------------- G1S: GEMMs (ldmatrix A) + single-pass scan -> g_hn ----------------
#define G1SMEM (13248 * 4)

__global__ void __launch_bounds__(256) k_g1s(const float* __restrict__ lAd,
                                             const float* __restrict__ ldtd,
                                             const float* __restrict__ lAs,
                                             const float* __restrict__ ldts,
                                             const int* __restrict__ kptr) {
    extern __shared__ __align__(16) unsigned dyn[];
    __shared__ int s_ticket;
    int tid = threadIdx.x, lane = tid & 31, w = tid >> 5;

    if (tid == 0) s_ticket = atomicAdd(&g_ticket, 1);
    __syncthreads();
    int ticket = s_ticket;
    int chain = ticket & (NCHAIN - 1);
    int pos   = ticket >> 6;
    int b = chain >> 4, blk = chain & 15;
    int tok0 = (b * NPOS + pos) * 128;

    unsigned* sB1 = dyn + ARSZ;            // 4096..6208
    unsigned* sB2 = dyn + ARSZ + BSZ;      // 6208..8320

    cpA_row<false>(sptr(dyn), g_xn + blk * 64, tok0, tid);
    cpcopy<528>(sptr(sB1), g_wf_seq + (size_t)blk * 528, tid);
    cpcopy<528>(sptr(sB2), g_wf_dep + (size_t)blk * 528, tid);
    cp_commit();
    cp_wait<0>();
    __syncthreads();

    float as_[8][4] = {}, ad_[8][4] = {};
    unsigned sAbase = sptr(dyn);
#pragma unroll
    for (int ks = 0; ks < 4; ks++) {
        unsigned a[4];
        ldsmA(a, sAbase, w, ks, lane);
#pragma unroll
        for (int nt = 0; nt < 8; nt++) {
            int off = (nt * 4 + ks) * BSLOT + lane * 2;
            unsigned bb[2];
            *reinterpret_cast<uint2*>(bb) = *reinterpret_cast<const uint2*>(&sB1[off]);
            mma_bf16(as_[nt], a, bb);
            *reinterpret_cast<uint2*>(bb) = *reinterpret_cast<const uint2*>(&sB2[off]);
            mma_bf16(ad_[nt], a, bb);
        }
    }
    __syncthreads();                  // staging dead; alias scan buffers

    float*    sD  = reinterpret_cast<float*>(dyn);           // [128][66] fp32
    unsigned* sHD = dyn + 8448;                              // [128][33] bf16x2
    float*    sS  = reinterpret_cast<float*>(dyn + 12672);   // [4][64]
    float*    sQ  = sS + 256;                                // [4][64]
    float*    sC  = sQ + 256;                                // [64]

    // epilogue: silu -> drive (fp32, smem) ; gain*silu -> hd (bf16x2, smem)
    {
        float Kf = (float)(*kptr);
        int g = lane >> 2, t = lane & 3;
        int rl0 = w * 16 + g;
#pragma unroll
        for (int nt = 0; nt < 8; nt++) {
            int nl = nt * 8 + t * 2;
            int gch = blk * 64 + nl;
            float gn0 = gain_of(gch, Kf, lAd, ldtd);
            float gn1 = gain_of(gch + 1, Kf, lAd, ldtd);
            *reinterpret_cast<float2*>(&sD[rl0 * SDS + nl]) =
                make_float2(siluf(as_[nt][0]), siluf(as_[nt][1]));
            *reinterpret_cast<float2*>(&sD[(rl0 + 8) * SDS + nl]) =
                make_float2(siluf(as_[nt][2]), siluf(as_[nt][3]));
            sHD[rl0 * 33 + (nl >> 1)] =
                pk(gn0 * siluf(ad_[nt][0]), gn1 * siluf(ad_[nt][1]));
            sHD[(rl0 + 8) * 33 + (nl >> 1)] =
                pk(gn0 * siluf(ad_[nt][2]), gn1 * siluf(ad_[nt][3]));
        }
    }
    __syncthreads();

    // scan thread mapping: ch = tid & 63, q = tid >> 6
    int ch = tid & 63, q = tid >> 6;
    int gch = blk * 64 + ch;
    float a  = decay1(lAs, ldts, gch);
    float la = __logf(a);
    float a32 = __expf(32.0f * la);
    float aT  = __expf(128.0f * la);

    // local quarter scan (in place)
    {
        float y = 0.0f;
        int base = q * 32;
#pragma unroll 8
        for (int s = 0; s < 32; s++) {
            float* p = &sD[(base + s) * SDS + ch];
            y = fmaf(a, y, *p);
            *p = y;
        }
        sS[q * 64 + ch] = y;
    }
    __syncthreads();

    // quarter combine + aggregate publish
    float agg = 0.0f;
    if (tid < 64) {
        float C = 0.0f;
#pragma unroll
        for (int q2 = 0; q2 < 4; q2++) {
            sQ[q2 * 64 + tid] = C;
            C = fmaf(C, a32, sS[q2 * 64 + tid]);
        }
        agg = C;
        g_aggv[(size_t)(chain * NPOS + pos) * 64 + tid] = agg;
    }
    __syncthreads();
    if (tid == 0) {
        __threadfence();
        st_rel(&g_state[chain * NPOS + pos], 1);
    }

    // lookback
    if (tid < 64) {
        float carry = 0.0f;
        if (pos > 0) {
            float f = 1.0f;
            int p = pos - 1;
            while (true) {
                int st;
                do { st = ld_acq(&g_state[chain * NPOS + p]); } while (st == 0);
                if (st == 2) {
                    carry = fmaf(f, g_incv[(size_t)(chain * NPOS + p) * 64 + tid], carry);
                    break;
                }
                carry = fmaf(f, g_aggv[(size_t)(chain * NPOS + p) * 64 + tid], carry);
                f *= aT;
                if (--p < 0) break;
            }
        }
        sC[tid] = carry;
        if (pos < NPOS - 1)
            g_incv[(size_t)(chain * NPOS + pos) * 64 + tid] = fmaf(carry, aT, agg);
    }
    __syncthreads();
    if (tid == 0 && pos < NPOS - 1) {
        __threadfence();
        st_rel(&g_state[chain * NPOS + pos], 2);
    }

    // final combine: h = local + eff_carry * a^(s+1) + hd
    {
        float carry = sC[ch];
        float a64 = a32 * a32;
        float aq = (q == 0) ? 1.0f : (q == 1) ? a32 : (q == 2) ? a64 : a64 * a32;
        float eff = fmaf(carry, aq, sQ[q * 64 + ch]);
        float pw = eff * a;
        int base = q * 32;
#pragma unroll 8
        for (int s = 0; s < 32; s++) {
            int row = base + s;
            unsigned hu = sHD[row * 33 + (ch >> 1)];
            float2 hp = __bfloat1622float2(*reinterpret_cast<__nv_bfloat162*>(&hu));
            float hdv = (ch & 1) ? hp.y : hp.x;
            float* p = &sD[row * SDS + ch];
            *p = *p + pw + hdv;
            pw *= a;
        }
    }
    __syncthreads();

    // pack + coalesced store of h -> g_hn
#pragma unroll
    for (int it = 0; it < 16; it++) {
        int idx = tid + it * 256;
        int row = idx >> 5;
        int c2  = idx & 31;
        float h0 = sD[row * SDS + c2 * 2];
        float h1 = sD[row * SDS + c2 * 2 + 1];
        *reinterpret_cast<unsigned*>(&g_hn[(size_t)(tok0 + row) * DD + blk * 64 + c2 * 2]) =
            pk(h0, h1);
    }
}

// ---------------- rstd: warp-per-token over g_hn -> g_rsh ----------------
__global__ void __launch_bounds__(256) k_rstd() {
    int w = threadIdx.x >> 5, lane = threadIdx.x & 31;
    int tok = blockIdx.x * 8 + w;
    const uint4* hr = reinterpret_cast<const uint4*>(g_hn + (size_t)tok * DD);
    float ss = 0.0f;
#pragma unroll
    for (int i = 0; i < 4; i++) {
        uint4 u = hr[lane + i * 32];
        float2 a0 = __bfloat1622float2(*reinterpret_cast<__nv_bfloat162*>(&u.x));
        float2 a1 = __bfloat1622float2(*reinterpret_cast<__nv_bfloat162*>(&u.y));
        float2 a2 = __bfloat1622float2(*reinterpret_cast<__nv_bfloat162*>(&u.z));
        float2 a3 = __bfloat1622float2(*reinterpret_cast<__nv_bfloat162*>(&u.w));
        ss += a0.x * a0.x + a0.y * a0.y + a1.x * a1.x + a1.y * a1.y
            + a2.x * a2.x + a2.y * a2.y + a3.x * a3.x + a3.y * a3.y;
    }
#pragma unroll
    for (int off = 16; off > 0; off >>= 1) ss += __shfl_xor_sync(0xffffffffu, ss, off);
    if (lane == 0) g_rsh[tok] = rsqrtf(ss * (1.0f / DD) + EPSV);
}

// ---------------- G2: fully-async A (row-major + ldmatrix), acc-side rsh ----------------
__device__ __forceinline__ void g2_cpA(unsigned dsm, int tok0, int gc, int tid) {
    if (gc < 16)      cpA_row<false>(dsm, g_hn + gc * 64, tok0, tid);
    else if (gc < 32) cpA_row<false>(dsm, g_xn + (gc - 16) * 64, tok0, tid);
    else              cpA_row<true >(dsm, g_xn + (gc - 32) * 64, tok0, tid);
}

#define G2SMEM ((2 * ARSZ + 2 * BSZ) * 4)   // 49664 bytes

__global__ void __launch_bounds__(256) k_g2() {
    extern __shared__ __align__(16) unsigned dsm[];
    unsigned* sA0 = dsm;
    unsigned* sA1 = dsm + ARSZ;
    unsigned* sB0 = dsm + 2 * ARSZ;
    unsigned* sB1 = sB0 + BSZ;
    int blk = blockIdx.y;
    int tok0 = blockIdx.x * 128;
    int tid = threadIdx.x, lane = tid & 31, w = tid >> 5;
    const uint4* wp = g_wf_post + (size_t)(blk * 3) * 528;
    int gc0 = blk * 3;

    g2_cpA(sptr(sA0), tok0, gc0 + 0, tid);
    cpcopy<528>(sptr(sB0), wp, tid);
    cp_commit();                              // group0: A0 + B0
    g2_cpA(sptr(sA1), tok0, gc0 + 1, tid);
    cpcopy<528>(sptr(sB1), wp + 528, tid);
    cp_commit();                              // group1: A1 + B1

    int g = lane >> 2, t = lane & 3;
    int r0 = tok0 + w * 16 + g;
    float rsh_a = g_rsh[r0];
    float rsh_b = g_rsh[r0 + 8];
    int hnc = 16 - gc0;
    hnc = hnc < 0 ? 0 : (hnc > 3 ? 3 : hnc);

    float acc[8][4] = {};
    cp_wait<1>();
    __syncthreads();
    mma_chunk128_lm(acc, sptr(sA0), sB0, w, lane);
    if (hnc == 1) scale_acc(acc, rsh_a, rsh_b);
    __syncthreads();

    g2_cpA(sptr(sA0), tok0, gc0 + 2, tid);
    cpcopy<528>(sptr(sB0), wp + 1056, tid);
    cp_commit();                              // group2: A2 + B2

    cp_wait<1>();
    __syncthreads();
    mma_chunk128_lm(acc, sptr(sA1), sB1, w, lane);
    if (hnc == 2) scale_acc(acc, rsh_a, rsh_b);
    __syncthreads();

    cp_wait<0>();
    __syncthreads();
    mma_chunk128_lm(acc, sptr(sA0), sB0, w, lane);
    if (hnc == 3) scale_acc(acc, rsh_a, rsh_b);

    // epilogue -> g_rf (fragment layout)
    unsigned* rf = (unsigned*)g_rf + ((size_t)((tok0 >> 7) * 16 + blk)) * ASZ128;
#pragma unroll
    for (int nt = 0; nt < 8; nt++) {
        int ks = nt >> 1, hi = nt & 1;
        unsigned* p = rf + (w * 4 + ks) * ASLOT + (g * 4 + t) * 4 + 2 * hi;
        p[0] = pk(siluf(acc[nt][0]), siluf(acc[nt][1]));
        p[1] = pk(siluf(acc[nt][2]), siluf(acc[nt][3]));
    }
}

// ---------------- G3: t = r @ lr_B^T (M=64, 2-stage cp.async pipeline) ----------------
__device__ __forceinline__ void g3_issue(unsigned dA, unsigned dB, int slab16, int halfoff,
                                         int kt, int tid) {
    cpcopy<528>(dA, g_rf + (size_t)(slab16 + kt) * 1056 + halfoff, tid);
    cpcopy<528>(dB, g_wf_lrB + (size_t)kt * 528, tid);
    cp_commit();
}

__global__ void __launch_bounds__(256) k_g3() {
    __shared__ __align__(16) unsigned smem[2 * ASZ64 + 2 * BSZ];
    unsigned* sAb[2] = { smem, smem + ASZ64 };
    unsigned* sBb[2] = { smem + 2 * ASZ64, smem + 2 * ASZ64 + BSZ };
    int tok0 = blockIdx.x * 64;
    int tid = threadIdx.x, lane = tid & 31, w = tid >> 5, wm = w & 3, wn = w >> 2;
    int slab16 = (tok0 >> 7) * 16;
    int halfoff = ((tok0 >> 6) & 1) * 528;

    g3_issue(sptr(sAb[0]), sptr(sBb[0]), slab16, halfoff, 0, tid);
    g3_issue(sptr(sAb[1]), sptr(sBb[1]), slab16, halfoff, 1, tid);

    float acc[4][4] = {};
#pragma unroll
    for (int kt = 0; kt < 16; kt++) {
        if (kt < 15) cp_wait<1>(); else cp_wait<0>();
        __syncthreads();
        mma_chunk64(acc, sAb[kt & 1], sBb[kt & 1], wm, wn, lane);
        __syncthreads();
        if (kt + 2 < 16)
            g3_issue(sptr(sAb[kt & 1]), sptr(sBb[kt & 1]), slab16, halfoff, kt + 2, tid);
    }

    int g = lane >> 2, t = lane & 3;
    int mtg = ((tok0 & 64) >> 4) + wm;
    unsigned* tf = (unsigned*)g_tf + (size_t)(tok0 >> 7) * ASZ128;
#pragma unroll
    for (int nt = 0; nt < 4; nt++) {
        int ng = wn * 4 + nt;
        int ks = ng >> 1, hi = ng & 1;
        unsigned* p = tf + (mtg * 4 + ks) * ASLOT + (g * 4 + t) * 4 + 2 * hi;
        p[0] = pk(acc[nt][0], acc[nt][1]);
        p[1] = pk(acc[nt][2], acc[nt][3]);
    }
}

// ---------------- G4: out = x + bd(r, w_local) + t @ lr_A^T (M=128) ----------------
#define G4SMEM (2 * (ASZ128 + BSZ) * 4)

__global__ void __launch_bounds__(256) k_g4(const float* __restrict__ x,
                                            float* __restrict__ out) {
    extern __shared__ __align__(16) unsigned dsm[];
    unsigned* sA0 = dsm;
    unsigned* sB0 = dsm + ASZ128;
    unsigned* sA1 = dsm + ASZ128 + BSZ;
    unsigned* sB1 = dsm + 2 * ASZ128 + BSZ;
    int blk = blockIdx.y;
    int tok0 = blockIdx.x * 128;
    int tid = threadIdx.x, lane = tid & 31, w = tid >> 5;
    int slab16 = (tok0 >> 7) * 16;

    cpcopy<1056>(sptr(sA0), g_rf + (size_t)(slab16 + blk) * 1056, tid);
    cpcopy<528>(sptr(sB0), g_wf_loc + (size_t)blk * 528, tid);
    cp_commit();
    cpcopy<1056>(sptr(sA1), g_tf + (size_t)(tok0 >> 7) * 1056, tid);
    cpcopy<528>(sptr(sB1), g_wf_lrA + (size_t)blk * 528, tid);
    cp_commit();

    float acc[8][4] = {};
    cp_wait<1>();
    __syncthreads();
    mma_chunk128_frag(acc, sA0, sB0, w, lane);
    cp_wait<0>();
    __syncthreads();
    mma_chunk128_frag(acc, sA1, sB1, w, lane);

    int g = lane >> 2, t = lane & 3;
    int r0 = tok0 + w * 16 + g;
#pragma unroll
    for (int nt = 0; nt < 8; nt++) {
        int n = blk * 64 + nt * 8 + t * 2;
        size_t i0 = (size_t)r0 * DD + n;
        size_t i1 = (size_t)(r0 + 8) * DD + n;
        float2 x0 = *reinterpret_cast<const float2*>(&x[i0]);
        float2 x1 = *reinterpret_cast<const float2*>(&x[i1]);
        *reinterpret_cast<float2*>(&out[i0]) = make_float2(x0.x + acc[nt][0], x0.y + acc[nt][1]);
        *reinterpret_cast<float2*>(&out[i1]) = make_float2(x1.x + acc[nt][2], x1.y + acc[nt][3]);
    }
}

// ---------------- launch ----------------
extern "C" void kernel_launch(void* const* d_in, const int* in_sizes, int n_in,
                              void* d_out, int out_size) {
    const float* x    = (const float*)d_in[0];
    const int*   actk = (const int*)  d_in[1];
    const float* wseq = (const float*)d_in[2];
    const float* wdep = (const float*)d_in[3];
    const float* wpost= (const float*)d_in[4];
    const float* wloc = (const float*)d_in[5];
    const float* lrA  = (const float*)d_in[6];
    const float* lrB  = (const float*)d_in[7];
    const float* lAs  = (const float*)d_in[8];
    const float* ldts = (const float*)d_in[9];
    const float* lAd  = (const float*)d_in[10];
    const float* ldtd = (const float*)d_in[11];
    float* out = (float*)d_out;

    static bool attr_done = false;
    if (!attr_done) {
        cudaFuncSetAttribute(k_g1s, cudaFuncAttributeMaxDynamicSharedMemorySize, G1SMEM);
        cudaFuncSetAttribute(k_g2,  cudaFuncAttributeMaxDynamicSharedMemorySize, G2SMEM);
        cudaFuncSetAttribute(k_g4,  cudaFuncAttributeMaxDynamicSharedMemorySize, G4SMEM);
        attr_done = true;
    }

    dim3 gGemm(NTOK / 128, NBLK);    // (128, 16)

    k_prep<<<128 + NTOK / 8, 256>>>(x, wseq, wdep, wloc, lrA, wpost, lrB);
    k_g1s<<<NT128 * 16, 256, G1SMEM>>>(lAd, ldtd, lAs, ldts, actk);
    k_rstd<<<NTOK / 8, 256>>>();
    k_g2<<<gGemm, 256, G2SMEM>>>();
    k_g3<<<NTOK / 64, 256>>>();
    k_g4<<<gGemm, 256, G4SMEM>>>(x, out);
}

// round 14
// speedup vs baseline: 1.1437x; 1.0116x over previous
#include <cuda_runtime.h>
#include <cuda_bf16.h>
#include <math.h>

// ---------------- problem constants ----------------
#define BB 4
#define TT_SEQ 4096
#define DD 1024
#define NTOK (BB*TT_SEQ)          // 16384
#define NBLK 16
#define BIP 192
#define RANKR 64
#define NMEM 128
#define EPSV 1.1920929e-07f
#define NT128 (NTOK/128)          // 128
#define NPOS 32
#define NCHAIN 64

// fragment-slot strides (B tiles and rf/tf activations)
#define ASLOT 132
#define BSLOT 66
#define BSZ (32*BSLOT)            // 2112 uints
#define ASZ64  (16*ASLOT)
#define ASZ128 (32*ASLOT)         // 4224 uints
#define ARSZ 4096                 // row-major A tile: 128 rows x 128B = 4096 uints
#define SDS 66

// ---------------- scratch (device globals; no allocation) ----------------
__device__ __nv_bfloat16 g_xn   [NTOK*DD];
__device__ __nv_bfloat16 g_hn   [NTOK*DD];
__device__ float g_rsx  [NTOK];
__device__ float g_rsh  [NTOK];

// decoupled-lookback state
__device__ int   g_ticket;
__device__ int   g_state[NCHAIN*NPOS];
__device__ float g_aggv [NCHAIN*NPOS*64];
__device__ float g_incv [NCHAIN*NPOS*64];

// fragment-major activations
__device__ uint4 g_rf[NT128*16*(ASZ128/4)];
__device__ uint4 g_tf[NT128*(ASZ128/4)];

// pre-fragmented bf16 weights
__device__ uint4 g_wf_seq [NBLK*BSZ/4];
__device__ uint4 g_wf_dep [NBLK*BSZ/4];
__device__ uint4 g_wf_loc [NBLK*BSZ/4];
__device__ uint4 g_wf_lrA [NBLK*BSZ/4];
__device__ uint4 g_wf_post[NBLK*3*BSZ/4];
__device__ uint4 g_wf_lrB [16*BSZ/4];

__device__ __forceinline__ float siluf(float x) {
    return x / (1.0f + __expf(-x));
}

__device__ __forceinline__ unsigned pk(float a, float b) {
    unsigned r;
    asm("cvt.rn.bf16x2.f32 %0, %1, %2;" : "=r"(r) : "f"(b), "f"(a));
    return r;
}

__device__ __forceinline__ float decay1(const float* __restrict__ lA,
                                        const float* __restrict__ ldt, int d) {
    return fmaxf(__expf(-__expf(lA[d]) * __expf(ldt[d])), 1e-6f);
}

// ---------------- acquire/release ----------------
__device__ __forceinline__ int ld_acq(const int* p) {
    int v;
    asm volatile("ld.global.acquire.gpu.b32 %0, [%1];" : "=r"(v) : "l"(p));
    return v;
}
__device__ __forceinline__ void st_rel(int* p, int v) {
    asm volatile("st.global.release.gpu.b32 [%0], %1;" :: "l"(p), "r"(v));
}

// ---------------- cp.async helpers ----------------
__device__ __forceinline__ unsigned sptr(const void* p) {
    return (unsigned)__cvta_generic_to_shared(p);
}
__device__ __forceinline__ void cpa16(unsigned d, const void* s) {
    asm volatile("cp.async.cg.shared.global [%0], [%1], 16;" :: "r"(d), "l"(s));
}
__device__ __forceinline__ void cpa16z(unsigned d, const void* s) {
    // src-size 0: no bytes read, 16B zero-filled
    asm volatile("cp.async.cg.shared.global [%0], [%1], 16, 0;" :: "r"(d), "l"(s));
}
__device__ __forceinline__ void cp_commit() {
    asm volatile("cp.async.commit_group;");
}
template<int N>
__device__ __forceinline__ void cp_wait() {
    asm volatile("cp.async.wait_group %0;" :: "n"(N));
}
template<int N4>
__device__ __forceinline__ void cpcopy(unsigned dsm, const uint4* __restrict__ src, int tid) {
#pragma unroll
    for (int i = tid; i < N4; i += 256) cpa16(dsm + i * 16, src + i);
}

// row-major A chunk copy: 128 tokens x 64 bf16 (128B/row), SW128 swizzle.
template<bool SHIFT>
__device__ __forceinline__ void cpA_row(unsigned dsm, const __nv_bfloat16* __restrict__ colbase,
                                        int tok0, int tid) {
#pragma unroll
    for (int it = 0; it < 4; ++it) {
        int idx = tid + it * 256;     // 0..1023
        int row = idx >> 3;
        int c16 = idx & 7;
        unsigned dst = dsm + row * 128 + ((c16 ^ (row & 7)) << 4);
        int tok = tok0 + row;
        if (SHIFT) {
            if ((tok & (TT_SEQ - 1)) == 0) cpa16z(dst, colbase);
            else cpa16(dst, colbase + (size_t)(tok - 1) * DD + c16 * 8);
        } else {
            cpa16(dst, colbase + (size_t)tok * DD + c16 * 8);
        }
    }
}

// ---------------- bf16 MMA machinery ----------------
__device__ __forceinline__ void mma_bf16(float c[4], const unsigned a[4], const unsigned b[2]) {
    asm volatile("mma.sync.aligned.m16n8k16.row.col.f32.bf16.bf16.f32 "
        "{%0,%1,%2,%3}, {%4,%5,%6,%7}, {%8,%9}, {%0,%1,%2,%3};"
        : "+f"(c[0]), "+f"(c[1]), "+f"(c[2]), "+f"(c[3])
        : "r"(a[0]), "r"(a[1]), "r"(a[2]), "r"(a[3]), "r"(b[0]), "r"(b[1]));
}

// ldmatrix x4: A fragment (m16 tile mt, k-chunk ks) from swizzled row-major tile
__device__ __forceinline__ void ldsmA(unsigned a[4], unsigned sAbase, int mt, int ks, int lane) {
    int row = mt * 16 + (lane & 7) + ((lane & 8) ? 8 : 0);
    int ci  = ks * 2 + ((lane & 16) ? 1 : 0);
    unsigned addr = sAbase + row * 128 + ((ci ^ (row & 7)) << 4);
    asm volatile("ldmatrix.sync.aligned.m8n8.x4.shared.b16 {%0,%1,%2,%3}, [%4];"
        : "=r"(a[0]), "=r"(a[1]), "=r"(a[2]), "=r"(a[3]) : "r"(addr));
}

// M=128 mma over row-major A (ldmatrix) and fragment-major B
__device__ __forceinline__ void mma_chunk128_lm(float acc[8][4], unsigned sAbase,
                                                const unsigned* sB, int w, int lane) {
#pragma unroll
    for (int ks = 0; ks < 4; ks++) {
        unsigned a[4];
        ldsmA(a, sAbase, w, ks, lane);
#pragma unroll
        for (int nt = 0; nt < 8; nt++) {
            unsigned b[2];
            *reinterpret_cast<uint2*>(b) =
                *reinterpret_cast<const uint2*>(&sB[(nt * 4 + ks) * BSLOT + lane * 2]);
            mma_bf16(acc[nt], a, b);
        }
    }
}

// M=64 fragment-major mma (g3 path)
__device__ __forceinline__ void mma_chunk64(float acc[4][4], const unsigned* sA,
                                            const unsigned* sB, int wm, int wn, int lane) {
#pragma unroll
    for (int ks = 0; ks < 4; ks++) {
        unsigned a[4];
        *reinterpret_cast<uint4*>(a) =
            *reinterpret_cast<const uint4*>(&sA[(wm * 4 + ks) * ASLOT + lane * 4]);
#pragma unroll
        for (int nt = 0; nt < 4; nt++) {
            unsigned b[2];
            *reinterpret_cast<uint2*>(b) =
                *reinterpret_cast<const uint2*>(&sB[((wn * 4 + nt) * 4 + ks) * BSLOT + lane * 2]);
            mma_bf16(acc[nt], a, b);
        }
    }
}

__device__ __forceinline__ void mma_chunk128_frag(float acc[8][4], const unsigned* sA,
                                                  const unsigned* sB, int w, int lane) {
#pragma unroll
    for (int ks = 0; ks < 4; ks++) {
        unsigned a[4];
        *reinterpret_cast<uint4*>(a) =
            *reinterpret_cast<const uint4*>(&sA[(w * 4 + ks) * ASLOT + lane * 4]);
#pragma unroll
        for (int nt = 0; nt < 8; nt++) {
            unsigned b[2];
            *reinterpret_cast<uint2*>(b) =
                *reinterpret_cast<const uint2*>(&sB[(nt * 4 + ks) * BSLOT + lane * 2]);
            mma_bf16(acc[nt], a, b);
        }
    }
}

__device__ __forceinline__ void scale_acc(float acc[8][4], float ra, float rb) {
#pragma unroll
    for (int nt = 0; nt < 8; nt++) {
        acc[nt][0] *= ra; acc[nt][1] *= ra;
        acc[nt][2] *= rb; acc[nt][3] *= rb;
    }
}

// ---------------- prep: flags + weight fragmentation + x stats ----------------
__global__ void __launch_bounds__(256) k_prep(const float* __restrict__ x,
                                              const float* __restrict__ wseq,
                                              const float* __restrict__ wdep,
                                              const float* __restrict__ wloc,
                                              const float* __restrict__ lrA,
                                              const float* __restrict__ wpost,
                                              const float* __restrict__ lrB) {
    int tid = threadIdx.x;
    if (blockIdx.x == 0) {
        if (tid == 0) g_ticket = 0;
        for (int i = tid; i < NCHAIN * NPOS; i += 256) g_state[i] = 0;
    }
    if (blockIdx.x < 128) {
        int t = blockIdx.x;
        const float* src;
        unsigned* dst;
        int rs;
        if (t < 16)       { src = wseq + (size_t)t * 4096; dst = (unsigned*)g_wf_seq + t * BSZ; rs = 64; }
        else if (t < 32)  { int b = t - 16; src = wdep + (size_t)b * 4096; dst = (unsigned*)g_wf_dep + b * BSZ; rs = 64; }
        else if (t < 48)  { int b = t - 32; src = wloc + (size_t)b * 4096; dst = (unsigned*)g_wf_loc + b * BSZ; rs = 64; }
        else if (t < 64)  { int b = t - 48; src = lrA + (size_t)b * 4096;  dst = (unsigned*)g_wf_lrA + b * BSZ; rs = 64; }
        else if (t < 112) { int i = t - 64; int b = i / 3, kt = i % 3;
                            src = wpost + (size_t)b * 64 * BIP + kt * 64;
                            dst = (unsigned*)g_wf_post + i * BSZ; rs = BIP; }
        else              { int kt = t - 112; src = lrB + kt * 64; dst = (unsigned*)g_wf_lrB + kt * BSZ; rs = DD; }
#pragma unroll
        for (int it = 0; it < 4; ++it) {
            int idx = tid + it * 256;
            int n  = idx >> 4;
            int k0 = (idx & 15) << 2;
            float4 v = *reinterpret_cast<const float4*>(src + (size_t)n * rs + k0);
            int nt = n >> 3, g = n & 7;
            int ks = k0 >> 4, kk = k0 & 15, hi = kk >> 3, t0 = (kk & 7) >> 1;
            unsigned* p = &dst[(nt * 4 + ks) * BSLOT + (g * 4 + t0) * 2 + hi];
            p[0] = pk(v.x, v.y);
            p[2] = pk(v.z, v.w);
        }
    } else {
        int w = tid >> 5, lane = tid & 31;
        int tok = (blockIdx.x - 128) * 8 + w;
        const float4* xr = reinterpret_cast<const float4*>(x + (size_t)tok * DD);
        float4 v[8];
        float ss = 0.0f;
#pragma unroll
        for (int i = 0; i < 8; i++) {
            v[i] = xr[lane + i * 32];
            ss += v[i].x * v[i].x + v[i].y * v[i].y + v[i].z * v[i].z + v[i].w * v[i].w;
        }
#pragma unroll
        for (int off = 16; off > 0; off >>= 1) ss += __shfl_xor_sync(0xffffffffu, ss, off);
        ss = __shfl_sync(0xffffffffu, ss, 0);
        float sc = rsqrtf(ss * (1.0f / DD) + EPSV);
        if (lane == 0) g_rsx[tok] = sc;
        uint2* xo = reinterpret_cast<uint2*>(g_xn + (size_t)tok * DD);
#pragma unroll
        for (int i = 0; i < 8; i++) {
            uint2 o;
            o.x = pk(v[i].x * sc, v[i].y * sc);
            o.y = pk(v[i].z * sc, v[i].w * sc);
            xo[lane + i * 32] = o;
        }
    }
}

// ---------------- gain helper ----------------
__device__ __forceinline__ float gain_of(int gch, float Kf, const float* __restrict__ lAd,
                                         const float* __restrict__ ldtd) {
    if (gch < NMEM) return Kf;
    float a1 = __expf(-__expf(lAd[gch - NMEM]) * __expf(ldtd[gch - NMEM]));
    float om = 1.0f - a1;
    if (fabsf(om) < 1e-6f) return Kf;
    return (1.0f - __expf(Kf * __logf(a1))) / fmaxf(om, 1e-8f);
}

// ---------------- G1S: GEMMs (ldmatrix A) + single-pass scan -> g_hn ----------------
#define G1SMEM (13248 * 4)

__global__ void __launch_bounds__(256) k_g1s(const float* __restrict__ lAd,
                                             const float* __restrict__ ldtd,
                                             const float* __restrict__ lAs,
                                             const float* __restrict__ ldts,
                                             const int* __restrict__ kptr) {
    extern __shared__ __align__(16) unsigned dyn[];
    __shared__ int s_ticket;
    int tid = threadIdx.x, lane = tid & 31, w = tid >> 5;

    if (tid == 0) s_ticket = atomicAdd(&g_ticket, 1);
    __syncthreads();
    int ticket = s_ticket;
    int chain = ticket & (NCHAIN - 1);
    int pos   = ticket >> 6;
    int b = chain >> 4, blk = chain & 15;
    int tok0 = (b * NPOS + pos) * 128;

    unsigned* sB1 = dyn + ARSZ;
    unsigned* sB2 = dyn + ARSZ + BSZ;

    cpA_row<false>(sptr(dyn), g_xn + blk * 64, tok0, tid);
    cpcopy<528>(sptr(sB1), g_wf_seq + (size_t)blk * 528, tid);
    cpcopy<528>(sptr(sB2), g_wf_dep + (size_t)blk * 528, tid);
    cp_commit();
    cp_wait<0>();
    __syncthreads();

    float as_[8][4] = {}, ad_[8][4] = {};
    unsigned sAbase = sptr(dyn);
#pragma unroll
    for (int ks = 0; ks < 4; ks++) {
        unsigned a[4];
        ldsmA(a, sAbase, w, ks, lane);
#pragma unroll
        for (int nt = 0; nt < 8; nt++) {
            int off = (nt * 4 + ks) * BSLOT + lane * 2;
            unsigned bb[2];
            *reinterpret_cast<uint2*>(bb) = *reinterpret_cast<const uint2*>(&sB1[off]);
            mma_bf16(as_[nt], a, bb);
            *reinterpret_cast<uint2*>(bb) = *reinterpret_cast<const uint2*>(&sB2[off]);
            mma_bf16(ad_[nt], a, bb);
        }
    }
    __syncthreads();                  // staging dead; alias scan buffers

    float*    sD  = reinterpret_cast<float*>(dyn);           // [128][66] fp32
    unsigned* sHD = dyn + 8448;                              // [128][33] bf16x2
    float*    sS  = reinterpret_cast<float*>(dyn + 12672);   // [4][64]
    float*    sQ  = sS + 256;                                // [4][64]
    float*    sC  = sQ + 256;                                // [64]

    // epilogue: silu -> drive (fp32, smem) ; gain*silu -> hd (bf16x2, smem)
    {
        float Kf = (float)(*kptr);
        int g = lane >> 2, t = lane & 3;
        int rl0 = w * 16 + g;
#pragma unroll
        for (int nt = 0; nt < 8; nt++) {
            int nl = nt * 8 + t * 2;
            int gch = blk * 64 + nl;
            float gn0 = gain_of(gch, Kf, lAd, ldtd);
            float gn1 = gain_of(gch + 1, Kf, lAd, ldtd);
            *reinterpret_cast<float2*>(&sD[rl0 * SDS + nl]) =
                make_float2(siluf(as_[nt][0]), siluf(as_[nt][1]));
            *reinterpret_cast<float2*>(&sD[(rl0 + 8) * SDS + nl]) =
                make_float2(siluf(as_[nt][2]), siluf(as_[nt][3]));
            sHD[rl0 * 33 + (nl >> 1)] =
                pk(gn0 * siluf(ad_[nt][0]), gn1 * siluf(ad_[nt][1]));
            sHD[(rl0 + 8) * 33 + (nl >> 1)] =
                pk(gn0 * siluf(ad_[nt][2]), gn1 * siluf(ad_[nt][3]));
        }
    }
    __syncthreads();

    // scan thread mapping: ch = tid & 63, q = tid >> 6
    int ch = tid & 63, q = tid >> 6;
    int gch = blk * 64 + ch;
    float a  = decay1(lAs, ldts, gch);
    float la = __logf(a);
    float a32 = __expf(32.0f * la);
    float aT  = __expf(128.0f * la);

    // local quarter scan (in place)
    {
        float y = 0.0f;
        int base = q * 32;
#pragma unroll 8
        for (int s = 0; s < 32; s++) {
            float* p = &sD[(base + s) * SDS + ch];
            y = fmaf(a, y, *p);
            *p = y;
        }
        sS[q * 64 + ch] = y;
    }
    __syncthreads();

    // quarter combine + aggregate publish
    float agg = 0.0f;
    if (tid < 64) {
        float C = 0.0f;
#pragma unroll
        for (int q2 = 0; q2 < 4; q2++) {
            sQ[q2 * 64 + tid] = C;
            C = fmaf(C, a32, sS[q2 * 64 + tid]);
        }
        agg = C;
        g_aggv[(size_t)(chain * NPOS + pos) * 64 + tid] = agg;
    }
    __syncthreads();
    if (tid == 0) {
        __threadfence();
        st_rel(&g_state[chain * NPOS + pos], 1);
    }

    // lookback
    if (tid < 64) {
        float carry = 0.0f;
        if (pos > 0) {
            float f = 1.0f;
            int p = pos - 1;
            while (true) {
                int st;
                do { st = ld_acq(&g_state[chain * NPOS + p]); } while (st == 0);
                if (st == 2) {
                    carry = fmaf(f, g_incv[(size_t)(chain * NPOS + p) * 64 + tid], carry);
                    break;
                }
                carry = fmaf(f, g_aggv[(size_t)(chain * NPOS + p) * 64 + tid], carry);
                f *= aT;
                if (--p < 0) break;
            }
        }
        sC[tid] = carry;
        if (pos < NPOS - 1)
            g_incv[(size_t)(chain * NPOS + pos) * 64 + tid] = fmaf(carry, aT, agg);
    }
    __syncthreads();
    if (tid == 0 && pos < NPOS - 1) {
        __threadfence();
        st_rel(&g_state[chain * NPOS + pos], 2);
    }

    // final combine: h = local + eff_carry * a^(s+1) + hd
    {
        float carry = sC[ch];
        float a64 = a32 * a32;
        float aq = (q == 0) ? 1.0f : (q == 1) ? a32 : (q == 2) ? a64 : a64 * a32;
        float eff = fmaf(carry, aq, sQ[q * 64 + ch]);
        float pw = eff * a;
        int base = q * 32;
#pragma unroll 8
        for (int s = 0; s < 32; s++) {
            int row = base + s;
            unsigned hu = sHD[row * 33 + (ch >> 1)];
            float2 hp = __bfloat1622float2(*reinterpret_cast<__nv_bfloat162*>(&hu));
            float hdv = (ch & 1) ? hp.y : hp.x;
            float* p = &sD[row * SDS + ch];
            *p = *p + pw + hdv;
            pw *= a;
        }
    }
    __syncthreads();

    // pack + coalesced store of h -> g_hn
#pragma unroll
    for (int it = 0; it < 16; it++) {
        int idx = tid + it * 256;
        int row = idx >> 5;
        int c2  = idx & 31;
        float h0 = sD[row * SDS + c2 * 2];
        float h1 = sD[row * SDS + c2 * 2 + 1];
        *reinterpret_cast<unsigned*>(&g_hn[(size_t)(tok0 + row) * DD + blk * 64 + c2 * 2]) =
            pk(h0, h1);
    }
}

// ---------------- rstd: warp-per-token over g_hn -> g_rsh ----------------
__global__ void __launch_bounds__(256) k_rstd() {
    int w = threadIdx.x >> 5, lane = threadIdx.x & 31;
    int tok = blockIdx.x * 8 + w;
    const uint4* hr = reinterpret_cast<const uint4*>(g_hn + (size_t)tok * DD);
    float ss = 0.0f;
#pragma unroll
    for (int i = 0; i < 4; i++) {
        uint4 u = hr[lane + i * 32];
        float2 a0 = __bfloat1622float2(*reinterpret_cast<__nv_bfloat162*>(&u.x));
        float2 a1 = __bfloat1622float2(*reinterpret_cast<__nv_bfloat162*>(&u.y));
        float2 a2 = __bfloat1622float2(*reinterpret_cast<__nv_bfloat162*>(&u.z));
        float2 a3 = __bfloat1622float2(*reinterpret_cast<__nv_bfloat162*>(&u.w));
        ss += a0.x * a0.x + a0.y * a0.y + a1.x * a1.x + a1.y * a1.y
            + a2.x * a2.x + a2.y * a2.y + a3.x * a3.x + a3.y * a3.y;
    }
#pragma unroll
    for (int off = 16; off > 0; off >>= 1) ss += __shfl_xor_sync(0xffffffffu, ss, off);
    if (lane == 0) g_rsh[tok] = rsqrtf(ss * (1.0f / DD) + EPSV);
}

// ---------------- G2: fully-async A (row-major + ldmatrix), acc-side rsh ----------------
__device__ __forceinline__ void g2_cpA(unsigned dsm, int tok0, int gc, int tid) {
    if (gc < 16)      cpA_row<false>(dsm, g_hn + gc * 64, tok0, tid);
    else if (gc < 32) cpA_row<false>(dsm, g_xn + (gc - 16) * 64, tok0, tid);
    else              cpA_row<true >(dsm, g_xn + (gc - 32) * 64, tok0, tid);
}

#define G2SMEM ((2 * ARSZ + 2 * BSZ) * 4)   // 49664 bytes

__global__ void __launch_bounds__(256, 4) k_g2() {
    extern __shared__ __align__(16) unsigned dsm[];
    unsigned* sA0 = dsm;
    unsigned* sA1 = dsm + ARSZ;
    unsigned* sB0 = dsm + 2 * ARSZ;
    unsigned* sB1 = sB0 + BSZ;
    int blk = blockIdx.y;
    int tok0 = blockIdx.x * 128;
    int tid = threadIdx.x, lane = tid & 31, w = tid >> 5;
    const uint4* wp = g_wf_post + (size_t)(blk * 3) * 528;
    int gc0 = blk * 3;

    g2_cpA(sptr(sA0), tok0, gc0 + 0, tid);
    cpcopy<528>(sptr(sB0), wp, tid);
    cp_commit();                              // group0: A0 + B0
    g2_cpA(sptr(sA1), tok0, gc0 + 1, tid);
    cpcopy<528>(sptr(sB1), wp + 528, tid);
    cp_commit();                              // group1: A1 + B1

    int g = lane >> 2, t = lane & 3;
    int r0 = tok0 + w * 16 + g;
    float rsh_a = g_rsh[r0];
    float rsh_b = g_rsh[r0 + 8];
    int hnc = 16 - gc0;
    hnc = hnc < 0 ? 0 : (hnc > 3 ? 3 : hnc);

    float acc[8][4] = {};
    cp_wait<1>();
    __syncthreads();
    mma_chunk128_lm(acc, sptr(sA0), sB0, w, lane);
    if (hnc == 1) scale_acc(acc, rsh_a, rsh_b);
    __syncthreads();

    g2_cpA(sptr(sA0), tok0, gc0 + 2, tid);
    cpcopy<528>(sptr(sB0), wp + 1056, tid);
    cp_commit();                              // group2: A2 + B2

    cp_wait<1>();
    __syncthreads();
    mma_chunk128_lm(acc, sptr(sA1), sB1, w, lane);
    if (hnc == 2) scale_acc(acc, rsh_a, rsh_b);
    __syncthreads();

    cp_wait<0>();
    __syncthreads();
    mma_chunk128_lm(acc, sptr(sA0), sB0, w, lane);
    if (hnc == 3) scale_acc(acc, rsh_a, rsh_b);

    // epilogue -> g_rf (fragment layout)
    unsigned* rf = (unsigned*)g_rf + ((size_t)((tok0 >> 7) * 16 + blk)) * ASZ128;
#pragma unroll
    for (int nt = 0; nt < 8; nt++) {
        int ks = nt >> 1, hi = nt & 1;
        unsigned* p = rf + (w * 4 + ks) * ASLOT + (g * 4 + t) * 4 + 2 * hi;
        p[0] = pk(siluf(acc[nt][0]), siluf(acc[nt][1]));
        p[1] = pk(siluf(acc[nt][2]), siluf(acc[nt][3]));
    }
}

// ---------------- G3: t = r @ lr_B^T (M=64, 2-stage cp.async pipeline) ----------------
__device__ __forceinline__ void g3_issue(unsigned dA, unsigned dB, int slab16, int halfoff,
                                         int kt, int tid) {
    cpcopy<528>(dA, g_rf + (size_t)(slab16 + kt) * 1056 + halfoff, tid);
    cpcopy<528>(dB, g_wf_lrB + (size_t)kt * 528, tid);
    cp_commit();
}

__global__ void __launch_bounds__(256) k_g3() {
    __shared__ __align__(16) unsigned smem[2 * ASZ64 + 2 * BSZ];
    unsigned* sAb[2] = { smem, smem + ASZ64 };
    unsigned* sBb[2] = { smem + 2 * ASZ64, smem + 2 * ASZ64 + BSZ };
    int tok0 = blockIdx.x * 64;
    int tid = threadIdx.x, lane = tid & 31, w = tid >> 5, wm = w & 3, wn = w >> 2;
    int slab16 = (tok0 >> 7) * 16;
    int halfoff = ((tok0 >> 6) & 1) * 528;

    g3_issue(sptr(sAb[0]), sptr(sBb[0]), slab16, halfoff, 0, tid);
    g3_issue(sptr(sAb[1]), sptr(sBb[1]), slab16, halfoff, 1, tid);

    float acc[4][4] = {};
#pragma unroll
    for (int kt = 0; kt < 16; kt++) {
        if (kt < 15) cp_wait<1>(); else cp_wait<0>();
        __syncthreads();
        mma_chunk64(acc, sAb[kt & 1], sBb[kt & 1], wm, wn, lane);
        __syncthreads();
        if (kt + 2 < 16)
            g3_issue(sptr(sAb[kt & 1]), sptr(sBb[kt & 1]), slab16, halfoff, kt + 2, tid);
    }

    int g = lane >> 2, t = lane & 3;
    int mtg = ((tok0 & 64) >> 4) + wm;
    unsigned* tf = (unsigned*)g_tf + (size_t)(tok0 >> 7) * ASZ128;
#pragma unroll
    for (int nt = 0; nt < 4; nt++) {
        int ng = wn * 4 + nt;
        int ks = ng >> 1, hi = ng & 1;
        unsigned* p = tf + (mtg * 4 + ks) * ASLOT + (g * 4 + t) * 4 + 2 * hi;
        p[0] = pk(acc[nt][0], acc[nt][1]);
        p[1] = pk(acc[nt][2], acc[nt][3]);
    }
}

// ---------------- G4: out = x + bd(r, w_local) + t @ lr_A^T (M=128) ----------------
#define G4SMEM (2 * (ASZ128 + BSZ) * 4)

__global__ void __launch_bounds__(256, 4) k_g4(const float* __restrict__ x,
                                               float* __restrict__ out) {
    extern __shared__ __align__(16) unsigned dsm[];
    unsigned* sA0 = dsm;
    unsigned* sB0 = dsm + ASZ128;
    unsigned* sA1 = dsm + ASZ128 + BSZ;
    unsigned* sB1 = dsm + 2 * ASZ128 + BSZ;
    int blk = blockIdx.y;
    int tok0 = blockIdx.x * 128;
    int tid = threadIdx.x, lane = tid & 31, w = tid >> 5;
    int slab16 = (tok0 >> 7) * 16;

    cpcopy<1056>(sptr(sA0), g_rf + (size_t)(slab16 + blk) * 1056, tid);
    cpcopy<528>(sptr(sB0), g_wf_loc + (size_t)blk * 528, tid);
    cp_commit();
    cpcopy<1056>(sptr(sA1), g_tf + (size_t)(tok0 >> 7) * 1056, tid);
    cpcopy<528>(sptr(sB1), g_wf_lrA + (size_t)blk * 528, tid);
    cp_commit();

    float acc[8][4] = {};
    cp_wait<1>();
    __syncthreads();
    mma_chunk128_frag(acc, sA0, sB0, w, lane);
    cp_wait<0>();
    __syncthreads();
    mma_chunk128_frag(acc, sA1, sB1, w, lane);

    int g = lane >> 2, t = lane & 3;
    int r0 = tok0 + w * 16 + g;
#pragma unroll
    for (int nt = 0; nt < 8; nt++) {
        int n = blk * 64 + nt * 8 + t * 2;
        size_t i0 = (size_t)r0 * DD + n;
        size_t i1 = (size_t)(r0 + 8) * DD + n;
        float2 x0 = *reinterpret_cast<const float2*>(&x[i0]);
        float2 x1 = *reinterpret_cast<const float2*>(&x[i1]);
        *reinterpret_cast<float2*>(&out[i0]) = make_float2(x0.x + acc[nt][0], x0.y + acc[nt][1]);
        *reinterpret_cast<float2*>(&out[i1]) = make_float2(x1.x + acc[nt][2], x1.y + acc[nt][3]);
    }
}

// ---------------- launch ----------------
extern "C" void kernel_launch(void* const* d_in, const int* in_sizes, int n_in,
                              void* d_out, int out_size) {
    const float* x    = (const float*)d_in[0];
    const int*   actk = (const int*)  d_in[1];
    const float* wseq = (const float*)d_in[2];
    const float* wdep = (const float*)d_in[3];
    const float* wpost= (const float*)d_in[4];
    const float* wloc = (const float*)d_in[5];
    const float* lrA  = (const float*)d_in[6];
    const float* lrB  = (const float*)d_in[7];
    const float* lAs  = (const float*)d_in[8];
    const float* ldts = (const float*)d_in[9];
    const float* lAd  = (const float*)d_in[10];
    const float* ldtd = (const float*)d_in[11];
    float* out = (float*)d_out;

    static bool attr_done = false;
    if (!attr_done) {
        cudaFuncSetAttribute(k_g1s, cudaFuncAttributeMaxDynamicSharedMemorySize, G1SMEM);
        cudaFuncSetAttribute(k_g2,  cudaFuncAttributeMaxDynamicSharedMemorySize, G2SMEM);
        cudaFuncSetAttribute(k_g4,  cudaFuncAttributeMaxDynamicSharedMemorySize, G4SMEM);
        attr_done = true;
    }

    dim3 gGemm(NTOK / 128, NBLK);    // (128, 16)

    k_prep<<<128 + NTOK / 8, 256>>>(x, wseq, wdep, wloc, lrA, wpost, lrB);
    k_g1s<<<NT128 * 16, 256, G1SMEM>>>(lAd, ldtd, lAs, ldts, actk);
    k_rstd<<<NTOK / 8, 256>>>();
    k_g2<<<gGemm, 256, G2SMEM>>>();
    k_g3<<<NTOK / 64, 256>>>();
    k_g4<<<gGemm, 256, G4SMEM>>>(x, out);
}